// round 7
// baseline (speedup 1.0000x reference)
#include <cuda_runtime.h>
#include <cstdint>

// GraphSAGE 2-layer, mean aggregation. Transform-then-aggregate:
//   y1 = x @ [W1_l; W1_r]^T ; agg1[dst]+=y1[src,0:64]; deg[dst]++ (in decode)
//   h  = relu(agg1/max(deg,1) + b1 + y1[:,64:128])
//   y2 = h @ [W2_l; W2_r]^T ; agg2[dst]+=y2[src,0:32]
//   out= agg2/max(deg,1) + b2 + y2[:,32:64]
// edge_index dtype auto-detected (JAX x64-disabled => int32 in practice).

#define MAXN 100000
#define MAXE 1600000
#define DIN 128
#define DH 64
#define DOUT 32

__device__ __align__(16) float g_y1[MAXN * (2 * DH)];   // [M][128]
__device__ __align__(16) float g_agg1[MAXN * DH];       // [M][64]
__device__ __align__(16) float g_h[MAXN * DH];          // [M][64]
__device__ __align__(16) float g_y2[MAXN * (2 * DOUT)]; // [M][64]
__device__ __align__(16) float g_agg2[MAXN * DOUT];     // [M][32]
__device__ __align__(16) float g_deg[MAXN];
__device__ __align__(16) int2  g_edge[MAXE];
__device__ int g_is64;

// ---------------------------------------------------------------------------
// Parallel dtype detect: int64 buffer => odd 32-bit words of first 128
// entries are all zero (values < 2^31). 128 threads + ballot.
// ---------------------------------------------------------------------------
__global__ void detect_kernel(const int* __restrict__ ei32, int nE) {
    int n = nE < 128 ? nE : 128;
    int tid = threadIdx.x;
    int bad = (tid < n && ei32[2 * tid + 1] != 0) ? 1 : 0;
    unsigned m = __ballot_sync(0xffffffffu, bad);
    __shared__ unsigned s[4];
    if ((tid & 31) == 0) s[tid >> 5] = m;
    __syncthreads();
    if (tid == 0) g_is64 = ((s[0] | s[1] | s[2] | s[3]) == 0u) ? 1 : 0;
}

// ---------------------------------------------------------------------------
// Decode edges into packed int2 {src,dst} AND accumulate in-degree.
// (zero_kernel must run before this.)
// ---------------------------------------------------------------------------
__global__ __launch_bounds__(256) void decode_kernel(const void* __restrict__ ei,
                                                     int nE) {
    int e = blockIdx.x * blockDim.x + threadIdx.x;
    if (e >= nE) return;
    int src, dst;
    if (g_is64) {
        const long long* p = (const long long*)ei;
        src = (int)p[e];
        dst = (int)p[nE + e];
    } else {
        const int* p = (const int*)ei;
        src = p[e];
        dst = p[nE + e];
    }
    g_edge[e] = make_int2(src, dst);
    atomicAdd(&g_deg[dst], 1.0f);
}

__global__ __launch_bounds__(256) void zero_kernel(int M) {
    int idx = blockIdx.x * blockDim.x + threadIdx.x;
    const int n1 = M * 16;
    const int n2 = M * 8;
    const int n3 = M / 4;
    float4 z = make_float4(0.f, 0.f, 0.f, 0.f);
    if (idx < n1) {
        ((float4*)g_agg1)[idx] = z;
    } else if (idx < n1 + n2) {
        ((float4*)g_agg2)[idx - n1] = z;
    } else if (idx < n1 + n2 + n3) {
        ((float4*)g_deg)[idx - n1 - n2] = z;
    }
}

// ---------------------------------------------------------------------------
// GEMM layer 1: Y[M][128] = X[M][128] @ [Wa(64x128); Wb(64x128)]^T
// BM=128, BN=128, BK=16, double-buffered smem, one sync per stage,
// LDG prefetch overlapped with compute. 8x8 split register tile.
// ---------------------------------------------------------------------------
__global__ __launch_bounds__(256) void gemm1(const float* __restrict__ X,
                                             const float* __restrict__ Wa,
                                             const float* __restrict__ Wb,
                                             int M) {
    __shared__ float Xs[2][16][132];
    __shared__ float Ws[2][16][132];

    const int tid = threadIdx.x;
    const int m0 = blockIdx.x * 128;
    const int tr = tid >> 4;        // 0..15
    const int tc = tid & 15;        // 0..15
    const int lrow = tid >> 2;      // 0..63
    const int lc4 = (tid & 3) * 4;  // 0,4,8,12

    const int gm0 = m0 + lrow;
    const int gm1 = m0 + lrow + 64;
    const float* wrow0 = Wa + (size_t)lrow * 128;   // rows 0..63
    const float* wrow1 = Wb + (size_t)lrow * 128;   // rows 64..127

    float4 pxa, pxb, pwa, pwb;
    const float4 fz = make_float4(0.f, 0.f, 0.f, 0.f);

#define G1_LOAD(k0)                                                        \
    do {                                                                   \
        pxa = (gm0 < M) ? *(const float4*)&X[(size_t)gm0 * 128 + (k0) + lc4] : fz; \
        pxb = (gm1 < M) ? *(const float4*)&X[(size_t)gm1 * 128 + (k0) + lc4] : fz; \
        pwa = *(const float4*)&wrow0[(k0) + lc4];                          \
        pwb = *(const float4*)&wrow1[(k0) + lc4];                          \
    } while (0)

#define G1_STORE(b)                                                        \
    do {                                                                   \
        Xs[b][lc4 + 0][lrow] = pxa.x; Xs[b][lc4 + 1][lrow] = pxa.y;        \
        Xs[b][lc4 + 2][lrow] = pxa.z; Xs[b][lc4 + 3][lrow] = pxa.w;        \
        Xs[b][lc4 + 0][lrow + 64] = pxb.x; Xs[b][lc4 + 1][lrow + 64] = pxb.y; \
        Xs[b][lc4 + 2][lrow + 64] = pxb.z; Xs[b][lc4 + 3][lrow + 64] = pxb.w; \
        Ws[b][lc4 + 0][lrow] = pwa.x; Ws[b][lc4 + 1][lrow] = pwa.y;        \
        Ws[b][lc4 + 2][lrow] = pwa.z; Ws[b][lc4 + 3][lrow] = pwa.w;        \
        Ws[b][lc4 + 0][lrow + 64] = pwb.x; Ws[b][lc4 + 1][lrow + 64] = pwb.y; \
        Ws[b][lc4 + 2][lrow + 64] = pwb.z; Ws[b][lc4 + 3][lrow + 64] = pwb.w; \
    } while (0)

    float acc[8][8];
#pragma unroll
    for (int i = 0; i < 8; i++)
#pragma unroll
        for (int j = 0; j < 8; j++) acc[i][j] = 0.f;

    G1_LOAD(0);
    G1_STORE(0);
    __syncthreads();

#pragma unroll
    for (int t = 0; t < 8; t++) {
        if (t < 7) G1_LOAD((t + 1) * 16);
        const int b = t & 1;
#pragma unroll
        for (int kk = 0; kk < 16; kk++) {
            float4 xa = *(const float4*)&Xs[b][kk][tr * 4];
            float4 xb = *(const float4*)&Xs[b][kk][64 + tr * 4];
            float4 wa = *(const float4*)&Ws[b][kk][tc * 4];
            float4 wb = *(const float4*)&Ws[b][kk][64 + tc * 4];
            float xv[8] = {xa.x, xa.y, xa.z, xa.w, xb.x, xb.y, xb.z, xb.w};
            float wv[8] = {wa.x, wa.y, wa.z, wa.w, wb.x, wb.y, wb.z, wb.w};
#pragma unroll
            for (int i = 0; i < 8; i++)
#pragma unroll
                for (int j = 0; j < 8; j++)
                    acc[i][j] = fmaf(xv[i], wv[j], acc[i][j]);
        }
        if (t < 7) {
            G1_STORE(b ^ 1);
            __syncthreads();
        }
    }

#pragma unroll
    for (int si = 0; si < 2; si++)
#pragma unroll
        for (int i = 0; i < 4; i++) {
            int m = m0 + si * 64 + tr * 4 + i;
            if (m < M) {
#pragma unroll
                for (int sj = 0; sj < 2; sj++) {
                    int a = si * 4 + i;
                    float4 v = make_float4(acc[a][sj * 4 + 0], acc[a][sj * 4 + 1],
                                           acc[a][sj * 4 + 2], acc[a][sj * 4 + 3]);
                    *(float4*)&g_y1[(size_t)m * 128 + sj * 64 + tc * 4] = v;
                }
            }
        }
#undef G1_LOAD
#undef G1_STORE
}

// ---------------------------------------------------------------------------
// GEMM layer 2: Y[M][64] = H[M][64] @ [Wa(32x64); Wb(32x64)]^T
// BM=128, BN=64, BK=16, double-buffered, 8x4 split tile.
// ---------------------------------------------------------------------------
__global__ __launch_bounds__(256) void gemm2(const float* __restrict__ Wa,
                                             const float* __restrict__ Wb,
                                             int M) {
    __shared__ float Xs[2][16][132];
    __shared__ float Ws[2][16][68];

    const int tid = threadIdx.x;
    const int m0 = blockIdx.x * 128;
    const int tr = tid >> 4;
    const int tc = tid & 15;
    const int lrow = tid >> 2;      // 0..63
    const int lc4 = (tid & 3) * 4;

    const int gm0 = m0 + lrow;
    const int gm1 = m0 + lrow + 64;
    const float* wrow = (lrow < 32) ? (Wa + (size_t)lrow * 64)
                                    : (Wb + (size_t)(lrow - 32) * 64);

    float4 pxa, pxb, pwa;
    const float4 fz = make_float4(0.f, 0.f, 0.f, 0.f);

#define G2_LOAD(k0)                                                        \
    do {                                                                   \
        pxa = (gm0 < M) ? *(const float4*)&g_h[(size_t)gm0 * 64 + (k0) + lc4] : fz; \
        pxb = (gm1 < M) ? *(const float4*)&g_h[(size_t)gm1 * 64 + (k0) + lc4] : fz; \
        pwa = *(const float4*)&wrow[(k0) + lc4];                           \
    } while (0)

#define G2_STORE(b)                                                        \
    do {                                                                   \
        Xs[b][lc4 + 0][lrow] = pxa.x; Xs[b][lc4 + 1][lrow] = pxa.y;        \
        Xs[b][lc4 + 2][lrow] = pxa.z; Xs[b][lc4 + 3][lrow] = pxa.w;        \
        Xs[b][lc4 + 0][lrow + 64] = pxb.x; Xs[b][lc4 + 1][lrow + 64] = pxb.y; \
        Xs[b][lc4 + 2][lrow + 64] = pxb.z; Xs[b][lc4 + 3][lrow + 64] = pxb.w; \
        Ws[b][lc4 + 0][lrow] = pwa.x; Ws[b][lc4 + 1][lrow] = pwa.y;        \
        Ws[b][lc4 + 2][lrow] = pwa.z; Ws[b][lc4 + 3][lrow] = pwa.w;        \
    } while (0)

    float acc[8][4];
#pragma unroll
    for (int i = 0; i < 8; i++)
#pragma unroll
        for (int j = 0; j < 4; j++) acc[i][j] = 0.f;

    G2_LOAD(0);
    G2_STORE(0);
    __syncthreads();

#pragma unroll
    for (int t = 0; t < 4; t++) {
        if (t < 3) G2_LOAD((t + 1) * 16);
        const int b = t & 1;
#pragma unroll
        for (int kk = 0; kk < 16; kk++) {
            float4 xa = *(const float4*)&Xs[b][kk][tr * 4];
            float4 xb = *(const float4*)&Xs[b][kk][64 + tr * 4];
            float4 wa = *(const float4*)&Ws[b][kk][tc * 4];
            float xv[8] = {xa.x, xa.y, xa.z, xa.w, xb.x, xb.y, xb.z, xb.w};
#pragma unroll
            for (int i = 0; i < 8; i++) {
                acc[i][0] = fmaf(xv[i], wa.x, acc[i][0]);
                acc[i][1] = fmaf(xv[i], wa.y, acc[i][1]);
                acc[i][2] = fmaf(xv[i], wa.z, acc[i][2]);
                acc[i][3] = fmaf(xv[i], wa.w, acc[i][3]);
            }
        }
        if (t < 3) {
            G2_STORE(b ^ 1);
            __syncthreads();
        }
    }

#pragma unroll
    for (int si = 0; si < 2; si++)
#pragma unroll
        for (int i = 0; i < 4; i++) {
            int m = m0 + si * 64 + tr * 4 + i;
            if (m < M) {
                int a = si * 4 + i;
                float4 v = make_float4(acc[a][0], acc[a][1], acc[a][2], acc[a][3]);
                *(float4*)&g_y2[(size_t)m * 64 + tc * 4] = v;
            }
        }
#undef G2_LOAD
#undef G2_STORE
}

// ---------------------------------------------------------------------------
// Edge scatter via vector red.add. 2 float4 per thread:
// 8 threads/edge (layer1, 64 floats), 4 threads/edge (layer2, 32 floats).
// ---------------------------------------------------------------------------
__device__ __forceinline__ void red_add_f4(float4* p, float4 v) {
    asm volatile("red.global.add.v4.f32 [%0], {%1, %2, %3, %4};"
                 :: "l"(p), "f"(v.x), "f"(v.y), "f"(v.z), "f"(v.w)
                 : "memory");
}

__global__ __launch_bounds__(256) void scatter1(int nE) {
    int idx = blockIdx.x * blockDim.x + threadIdx.x;
    if (idx >= nE * 8) return;
    int e = idx >> 3;
    int c = idx & 7;
    int2 ed = __ldg(&g_edge[e]);
    const float4* ys = (const float4*)g_y1 + (size_t)ed.x * 32;
    float4 v0 = __ldg(ys + c);
    float4 v1 = __ldg(ys + c + 8);
    float4* ad = (float4*)g_agg1 + (size_t)ed.y * 16;
    red_add_f4(ad + c, v0);
    red_add_f4(ad + c + 8, v1);
}

__global__ __launch_bounds__(256) void scatter2(int nE) {
    int idx = blockIdx.x * blockDim.x + threadIdx.x;
    if (idx >= nE * 4) return;
    int e = idx >> 2;
    int c = idx & 3;
    int2 ed = __ldg(&g_edge[e]);
    const float4* ys = (const float4*)g_y2 + (size_t)ed.x * 16;
    float4 v0 = __ldg(ys + c);
    float4 v1 = __ldg(ys + c + 4);
    float4* ad = (float4*)g_agg2 + (size_t)ed.y * 8;
    red_add_f4(ad + c, v0);
    red_add_f4(ad + c + 4, v1);
}

// ---------------------------------------------------------------------------
__global__ __launch_bounds__(256) void combine1(const float4* __restrict__ b1,
                                                int M) {
    int idx = blockIdx.x * blockDim.x + threadIdx.x;
    if (idx >= M * 16) return;
    int i = idx >> 4;
    int c = idx & 15;
    float inv = 1.0f / fmaxf(g_deg[i], 1.0f);
    float4 a = ((const float4*)g_agg1)[idx];
    float4 r = ((const float4*)g_y1)[(size_t)i * 32 + 16 + c];
    float4 b = __ldg(&b1[c]);
    float4 o;
    o.x = fmaxf(fmaf(a.x, inv, b.x + r.x), 0.f);
    o.y = fmaxf(fmaf(a.y, inv, b.y + r.y), 0.f);
    o.z = fmaxf(fmaf(a.z, inv, b.z + r.z), 0.f);
    o.w = fmaxf(fmaf(a.w, inv, b.w + r.w), 0.f);
    ((float4*)g_h)[idx] = o;
}

__global__ __launch_bounds__(256) void final_kernel(const float4* __restrict__ b2,
                                                    float* __restrict__ out, int M) {
    int idx = blockIdx.x * blockDim.x + threadIdx.x;
    if (idx >= M * 8) return;
    int i = idx >> 3;
    int c = idx & 7;
    float inv = 1.0f / fmaxf(g_deg[i], 1.0f);
    float4 a = ((const float4*)g_agg2)[idx];
    float4 r = ((const float4*)g_y2)[(size_t)i * 16 + 8 + c];
    float4 b = __ldg(&b2[c]);
    float4 o;
    o.x = fmaf(a.x, inv, b.x + r.x);
    o.y = fmaf(a.y, inv, b.y + r.y);
    o.z = fmaf(a.z, inv, b.z + r.z);
    o.w = fmaf(a.w, inv, b.w + r.w);
    ((float4*)out)[idx] = o;
}

// ---------------------------------------------------------------------------
static inline int cdiv(int a, int b) { return (a + b - 1) / b; }

extern "C" void kernel_launch(void* const* d_in, const int* in_sizes, int n_in,
                              void* d_out, int out_size) {
    const float* x    = (const float*)d_in[0];
    const void*  ei   = d_in[1];
    const float* W1l  = (const float*)d_in[2];
    const float* b1   = (const float*)d_in[3];
    const float* W1r  = (const float*)d_in[4];
    const float* W2l  = (const float*)d_in[5];
    const float* b2   = (const float*)d_in[6];
    const float* W2r  = (const float*)d_in[7];
    float* out = (float*)d_out;

    const int M  = in_sizes[0] / DIN;   // 100000
    const int nE = in_sizes[1] / 2;     // 1600000

    detect_kernel<<<1, 128>>>((const int*)ei, nE);
    {
        int tot = M * 16 + M * 8 + M / 4;
        zero_kernel<<<cdiv(tot, 256), 256>>>(M);
    }
    decode_kernel<<<cdiv(nE, 256), 256>>>(ei, nE);   // also builds deg
    gemm1<<<cdiv(M, 128), 256>>>(x, W1l, W1r, M);
    scatter1<<<cdiv(nE * 8, 256), 256>>>(nE);
    combine1<<<cdiv(M * 16, 256), 256>>>((const float4*)b1, M);
    gemm2<<<cdiv(M, 128), 256>>>(W2l, W2r, M);
    scatter2<<<cdiv(nE * 4, 256), 256>>>(nE);
    final_kernel<<<cdiv(M * 8, 256), 256>>>((const float4*)b2, out, M);
}

// round 8
// speedup vs baseline: 1.1274x; 1.1274x over previous
#include <cuda_runtime.h>
#include <cstdint>

// GraphSAGE 2-layer, mean aggregation. Transform-then-aggregate:
//   y1 = x @ [W1_l; W1_r]^T ; agg1[dst]+=y1[src,0:64]; deg[dst]++ (in decode)
//   h  = relu(agg1/max(deg,1) + b1 + y1[:,64:128])
//   y2 = h @ [W2_l; W2_r]^T ; agg2[dst]+=y2[src,0:32]
//   out= agg2/max(deg,1) + b2 + y2[:,32:64]
// GEMMs use packed fma.rn.f32x2 (FFMA2): scalar FFMA-3reg is half-rate
// (rt_SMSP=2) on Blackwell; f32x2 doubles MACs/instruction at full precision.

#define MAXN 100000
#define MAXE 1600000
#define DIN 128
#define DH 64
#define DOUT 32

typedef unsigned long long ull;

__device__ __align__(16) float g_y1[MAXN * (2 * DH)];   // [M][128]
__device__ __align__(16) float g_agg1[MAXN * DH];       // [M][64]
__device__ __align__(16) float g_h[MAXN * DH];          // [M][64]
__device__ __align__(16) float g_y2[MAXN * (2 * DOUT)]; // [M][64]
__device__ __align__(16) float g_agg2[MAXN * DOUT];     // [M][32]
__device__ __align__(16) float g_deg[MAXN];
__device__ __align__(16) int2  g_edge[MAXE];
__device__ int g_is64;

// ---------------------------------------------------------------------------
__device__ __forceinline__ ull pack2(float x, float y) {
    ull r;
    asm("mov.b64 %0, {%1, %2};" : "=l"(r) : "f"(x), "f"(y));
    return r;
}
__device__ __forceinline__ void fma2(ull& d, ull a, ull b) {
    asm("fma.rn.f32x2 %0, %1, %2, %0;" : "+l"(d) : "l"(a), "l"(b));
}
__device__ __forceinline__ void unpack2(float& x, float& y, ull v) {
    asm("mov.b64 {%0, %1}, %2;" : "=f"(x), "=f"(y) : "l"(v));
}

// ---------------------------------------------------------------------------
// Parallel dtype detect: int64 buffer => odd 32-bit words of first 128
// entries are all zero (values < 2^31).
// ---------------------------------------------------------------------------
__global__ void detect_kernel(const int* __restrict__ ei32, int nE) {
    int n = nE < 128 ? nE : 128;
    int tid = threadIdx.x;
    int bad = (tid < n && ei32[2 * tid + 1] != 0) ? 1 : 0;
    unsigned m = __ballot_sync(0xffffffffu, bad);
    __shared__ unsigned s[4];
    if ((tid & 31) == 0) s[tid >> 5] = m;
    __syncthreads();
    if (tid == 0) g_is64 = ((s[0] | s[1] | s[2] | s[3]) == 0u) ? 1 : 0;
}

// ---------------------------------------------------------------------------
// Decode edges into packed int2 {src,dst} AND accumulate in-degree.
// (zero_kernel must run before this.)
// ---------------------------------------------------------------------------
__global__ __launch_bounds__(256) void decode_kernel(const void* __restrict__ ei,
                                                     int nE) {
    int e = blockIdx.x * blockDim.x + threadIdx.x;
    if (e >= nE) return;
    int src, dst;
    if (g_is64) {
        const long long* p = (const long long*)ei;
        src = (int)p[e];
        dst = (int)p[nE + e];
    } else {
        const int* p = (const int*)ei;
        src = p[e];
        dst = p[nE + e];
    }
    g_edge[e] = make_int2(src, dst);
    atomicAdd(&g_deg[dst], 1.0f);
}

__global__ __launch_bounds__(256) void zero_kernel(int M) {
    int idx = blockIdx.x * blockDim.x + threadIdx.x;
    const int n1 = M * 16;
    const int n2 = M * 8;
    const int n3 = M / 4;
    float4 z = make_float4(0.f, 0.f, 0.f, 0.f);
    if (idx < n1) {
        ((float4*)g_agg1)[idx] = z;
    } else if (idx < n1 + n2) {
        ((float4*)g_agg2)[idx - n1] = z;
    } else if (idx < n1 + n2 + n3) {
        ((float4*)g_deg)[idx - n1 - n2] = z;
    }
}

// ---------------------------------------------------------------------------
// GEMM layer 1: Y[M][128] = X[M][128] @ [Wa(64x128); Wb(64x128)]^T
// BM=128, BN=128, BK=16, single-buffered (R6 structure), 8x8 split tile,
// inner product via packed FFMA2: 4 LDS.128 + 32 fma.f32x2 per kk.
// ---------------------------------------------------------------------------
__global__ __launch_bounds__(256, 2) void gemm1(const float* __restrict__ X,
                                                const float* __restrict__ Wa,
                                                const float* __restrict__ Wb,
                                                int M) {
    __shared__ float Xs[16][132];
    __shared__ float Ws[16][132];

    const int tid = threadIdx.x;
    const int m0 = blockIdx.x * 128;
    const int tr = tid >> 4;        // 0..15
    const int tc = tid & 15;        // 0..15
    const int lrow = tid >> 2;      // 0..63
    const int lc4 = (tid & 3) * 4;  // 0,4,8,12

    ull acc[8][4];                  // 8 rows x 4 col-pairs (f32x2)
#pragma unroll
    for (int i = 0; i < 8; i++)
#pragma unroll
        for (int j = 0; j < 4; j++) acc[i][j] = 0ull;

    for (int k0 = 0; k0 < 128; k0 += 16) {
#pragma unroll
        for (int s = 0; s < 2; s++) {
            int r = lrow + s * 64;
            int gm = m0 + r;
            float4 v = make_float4(0.f, 0.f, 0.f, 0.f);
            if (gm < M) v = *(const float4*)&X[(size_t)gm * 128 + k0 + lc4];
            Xs[lc4 + 0][r] = v.x; Xs[lc4 + 1][r] = v.y;
            Xs[lc4 + 2][r] = v.z; Xs[lc4 + 3][r] = v.w;
        }
#pragma unroll
        for (int s = 0; s < 2; s++) {
            int n = lrow + s * 64;
            const float* w = (n < 64) ? (Wa + (size_t)n * 128)
                                      : (Wb + (size_t)(n - 64) * 128);
            float4 v = *(const float4*)&w[k0 + lc4];
            Ws[lc4 + 0][n] = v.x; Ws[lc4 + 1][n] = v.y;
            Ws[lc4 + 2][n] = v.z; Ws[lc4 + 3][n] = v.w;
        }
        __syncthreads();

#pragma unroll
        for (int kk = 0; kk < 16; kk++) {
            float4 xa = *(const float4*)&Xs[kk][tr * 4];
            float4 xb = *(const float4*)&Xs[kk][64 + tr * 4];
            float4 wa = *(const float4*)&Ws[kk][tc * 4];
            float4 wb = *(const float4*)&Ws[kk][64 + tc * 4];
            ull wp[4] = {pack2(wa.x, wa.y), pack2(wa.z, wa.w),
                         pack2(wb.x, wb.y), pack2(wb.z, wb.w)};
            float xv[8] = {xa.x, xa.y, xa.z, xa.w, xb.x, xb.y, xb.z, xb.w};
#pragma unroll
            for (int i = 0; i < 8; i++) {
                ull xd = pack2(xv[i], xv[i]);
#pragma unroll
                for (int j = 0; j < 4; j++) fma2(acc[i][j], xd, wp[j]);
            }
        }
        __syncthreads();
    }

#pragma unroll
    for (int si = 0; si < 2; si++)
#pragma unroll
        for (int i = 0; i < 4; i++) {
            int m = m0 + si * 64 + tr * 4 + i;
            if (m < M) {
                int a = si * 4 + i;
#pragma unroll
                for (int sj = 0; sj < 2; sj++) {
                    float4 v;
                    unpack2(v.x, v.y, acc[a][sj * 2 + 0]);
                    unpack2(v.z, v.w, acc[a][sj * 2 + 1]);
                    *(float4*)&g_y1[(size_t)m * 128 + sj * 64 + tc * 4] = v;
                }
            }
        }
}

// ---------------------------------------------------------------------------
// GEMM layer 2: Y[M][64] = H[M][64] @ [Wa(32x64); Wb(32x64)]^T
// BM=128, BN=64, BK=16, 8x4 split tile, FFMA2 inner loop.
// ---------------------------------------------------------------------------
__global__ __launch_bounds__(256, 2) void gemm2(const float* __restrict__ Wa,
                                                const float* __restrict__ Wb,
                                                int M) {
    __shared__ float Xs[16][132];
    __shared__ float Ws[16][68];

    const int tid = threadIdx.x;
    const int m0 = blockIdx.x * 128;
    const int tr = tid >> 4;
    const int tc = tid & 15;
    const int lrow = tid >> 2;      // 0..63
    const int lc4 = (tid & 3) * 4;

    ull acc[8][2];
#pragma unroll
    for (int i = 0; i < 8; i++) { acc[i][0] = 0ull; acc[i][1] = 0ull; }

    for (int k0 = 0; k0 < 64; k0 += 16) {
#pragma unroll
        for (int s = 0; s < 2; s++) {
            int r = lrow + s * 64;
            int gm = m0 + r;
            float4 v = make_float4(0.f, 0.f, 0.f, 0.f);
            if (gm < M) v = *(const float4*)&g_h[(size_t)gm * 64 + k0 + lc4];
            Xs[lc4 + 0][r] = v.x; Xs[lc4 + 1][r] = v.y;
            Xs[lc4 + 2][r] = v.z; Xs[lc4 + 3][r] = v.w;
        }
        {
            int n = lrow;  // 0..63
            const float* w = (n < 32) ? (Wa + (size_t)n * 64)
                                      : (Wb + (size_t)(n - 32) * 64);
            float4 v = *(const float4*)&w[k0 + lc4];
            Ws[lc4 + 0][n] = v.x; Ws[lc4 + 1][n] = v.y;
            Ws[lc4 + 2][n] = v.z; Ws[lc4 + 3][n] = v.w;
        }
        __syncthreads();

#pragma unroll
        for (int kk = 0; kk < 16; kk++) {
            float4 xa = *(const float4*)&Xs[kk][tr * 4];
            float4 xb = *(const float4*)&Xs[kk][64 + tr * 4];
            float4 wa = *(const float4*)&Ws[kk][tc * 4];
            ull wp[2] = {pack2(wa.x, wa.y), pack2(wa.z, wa.w)};
            float xv[8] = {xa.x, xa.y, xa.z, xa.w, xb.x, xb.y, xb.z, xb.w};
#pragma unroll
            for (int i = 0; i < 8; i++) {
                ull xd = pack2(xv[i], xv[i]);
                fma2(acc[i][0], xd, wp[0]);
                fma2(acc[i][1], xd, wp[1]);
            }
        }
        __syncthreads();
    }

#pragma unroll
    for (int si = 0; si < 2; si++)
#pragma unroll
        for (int i = 0; i < 4; i++) {
            int m = m0 + si * 64 + tr * 4 + i;
            if (m < M) {
                int a = si * 4 + i;
                float4 v;
                unpack2(v.x, v.y, acc[a][0]);
                unpack2(v.z, v.w, acc[a][1]);
                *(float4*)&g_y2[(size_t)m * 64 + tc * 4] = v;
            }
        }
}

// ---------------------------------------------------------------------------
// Edge scatter via vector red.add. 2 float4 per thread:
// 8 threads/edge (layer1), 4 threads/edge (layer2).
// ---------------------------------------------------------------------------
__device__ __forceinline__ void red_add_f4(float4* p, float4 v) {
    asm volatile("red.global.add.v4.f32 [%0], {%1, %2, %3, %4};"
                 :: "l"(p), "f"(v.x), "f"(v.y), "f"(v.z), "f"(v.w)
                 : "memory");
}

__global__ __launch_bounds__(256) void scatter1(int nE) {
    int idx = blockIdx.x * blockDim.x + threadIdx.x;
    if (idx >= nE * 8) return;
    int e = idx >> 3;
    int c = idx & 7;
    int2 ed = __ldg(&g_edge[e]);
    const float4* ys = (const float4*)g_y1 + (size_t)ed.x * 32;
    float4 v0 = __ldg(ys + c);
    float4 v1 = __ldg(ys + c + 8);
    float4* ad = (float4*)g_agg1 + (size_t)ed.y * 16;
    red_add_f4(ad + c, v0);
    red_add_f4(ad + c + 8, v1);
}

__global__ __launch_bounds__(256) void scatter2(int nE) {
    int idx = blockIdx.x * blockDim.x + threadIdx.x;
    if (idx >= nE * 4) return;
    int e = idx >> 2;
    int c = idx & 3;
    int2 ed = __ldg(&g_edge[e]);
    const float4* ys = (const float4*)g_y2 + (size_t)ed.x * 16;
    float4 v0 = __ldg(ys + c);
    float4 v1 = __ldg(ys + c + 4);
    float4* ad = (float4*)g_agg2 + (size_t)ed.y * 8;
    red_add_f4(ad + c, v0);
    red_add_f4(ad + c + 4, v1);
}

// ---------------------------------------------------------------------------
__global__ __launch_bounds__(256) void combine1(const float4* __restrict__ b1,
                                                int M) {
    int idx = blockIdx.x * blockDim.x + threadIdx.x;
    if (idx >= M * 16) return;
    int i = idx >> 4;
    int c = idx & 15;
    float inv = 1.0f / fmaxf(g_deg[i], 1.0f);
    float4 a = ((const float4*)g_agg1)[idx];
    float4 r = ((const float4*)g_y1)[(size_t)i * 32 + 16 + c];
    float4 b = __ldg(&b1[c]);
    float4 o;
    o.x = fmaxf(fmaf(a.x, inv, b.x + r.x), 0.f);
    o.y = fmaxf(fmaf(a.y, inv, b.y + r.y), 0.f);
    o.z = fmaxf(fmaf(a.z, inv, b.z + r.z), 0.f);
    o.w = fmaxf(fmaf(a.w, inv, b.w + r.w), 0.f);
    ((float4*)g_h)[idx] = o;
}

__global__ __launch_bounds__(256) void final_kernel(const float4* __restrict__ b2,
                                                    float* __restrict__ out, int M) {
    int idx = blockIdx.x * blockDim.x + threadIdx.x;
    if (idx >= M * 8) return;
    int i = idx >> 3;
    int c = idx & 7;
    float inv = 1.0f / fmaxf(g_deg[i], 1.0f);
    float4 a = ((const float4*)g_agg2)[idx];
    float4 r = ((const float4*)g_y2)[(size_t)i * 16 + 8 + c];
    float4 b = __ldg(&b2[c]);
    float4 o;
    o.x = fmaf(a.x, inv, b.x + r.x);
    o.y = fmaf(a.y, inv, b.y + r.y);
    o.z = fmaf(a.z, inv, b.z + r.z);
    o.w = fmaf(a.w, inv, b.w + r.w);
    ((float4*)out)[idx] = o;
}

// ---------------------------------------------------------------------------
static inline int cdiv(int a, int b) { return (a + b - 1) / b; }

extern "C" void kernel_launch(void* const* d_in, const int* in_sizes, int n_in,
                              void* d_out, int out_size) {
    const float* x    = (const float*)d_in[0];
    const void*  ei   = d_in[1];
    const float* W1l  = (const float*)d_in[2];
    const float* b1   = (const float*)d_in[3];
    const float* W1r  = (const float*)d_in[4];
    const float* W2l  = (const float*)d_in[5];
    const float* b2   = (const float*)d_in[6];
    const float* W2r  = (const float*)d_in[7];
    float* out = (float*)d_out;

    const int M  = in_sizes[0] / DIN;   // 100000
    const int nE = in_sizes[1] / 2;     // 1600000

    detect_kernel<<<1, 128>>>((const int*)ei, nE);
    {
        int tot = M * 16 + M * 8 + M / 4;
        zero_kernel<<<cdiv(tot, 256), 256>>>(M);
    }
    decode_kernel<<<cdiv(nE, 256), 256>>>(ei, nE);   // also builds deg
    gemm1<<<cdiv(M, 128), 256>>>(x, W1l, W1r, M);
    scatter1<<<cdiv(nE * 8, 256), 256>>>(nE);
    combine1<<<cdiv(M * 16, 256), 256>>>((const float4*)b1, M);
    gemm2<<<cdiv(M, 128), 256>>>(W2l, W2r, M);
    scatter2<<<cdiv(nE * 4, 256), 256>>>(nE);
    final_kernel<<<cdiv(M * 8, 256), 256>>>((const float4*)b2, out, M);
}

// round 9
// speedup vs baseline: 1.3513x; 1.1986x over previous
#include <cuda_runtime.h>
#include <cstdint>

// GraphSAGE 2-layer, mean aggregation. Transform-then-aggregate + CSR-gather:
//   y1 = x @ [W1_l; W1_r]^T                       (FFMA2 GEMM)
//   CSR build: histogram -> exclusive scan -> fill
//   h  = relu(gather-mean(y1[:,0:64]) + b1 + y1[:,64:128])   (warp/dst gather)
//   y2 = h @ [W2_l; W2_r]^T
//   out= gather-mean(y2[:,0:32]) + b2 + y2[:,32:64]
// Gather replaces red.add scatters: write volume drops 16x, no atomic ALU.

#define MAXN 100000
#define MAXE 1600000
#define DIN 128
#define DH 64
#define DOUT 32

typedef unsigned long long ull;

__device__ __align__(16) float g_y1[MAXN * (2 * DH)];   // [M][128]
__device__ __align__(16) float g_h[MAXN * DH];          // [M][64]
__device__ __align__(16) float g_y2[MAXN * (2 * DOUT)]; // [M][64]
__device__ __align__(16) int2  g_edge[MAXE];
__device__ __align__(16) int   g_adj[MAXE];             // CSR adjacency (src)
__device__ __align__(16) int   g_rowstart[MAXN + 1];
__device__ __align__(16) int   g_degi[MAXN];
__device__ __align__(16) int   g_cnt[MAXN];
__device__ __align__(16) int   g_blocksums[512];
__device__ int g_is64;

// ---------------------------------------------------------------------------
__device__ __forceinline__ ull pack2(float x, float y) {
    ull r;
    asm("mov.b64 %0, {%1, %2};" : "=l"(r) : "f"(x), "f"(y));
    return r;
}
__device__ __forceinline__ void fma2(ull& d, ull a, ull b) {
    asm("fma.rn.f32x2 %0, %1, %2, %0;" : "+l"(d) : "l"(a), "l"(b));
}
__device__ __forceinline__ void unpack2(float& x, float& y, ull v) {
    asm("mov.b64 {%0, %1}, %2;" : "=f"(x), "=f"(y) : "l"(v));
}

// ---------------------------------------------------------------------------
__global__ void detect_kernel(const int* __restrict__ ei32, int nE) {
    int n = nE < 128 ? nE : 128;
    int tid = threadIdx.x;
    int bad = (tid < n && ei32[2 * tid + 1] != 0) ? 1 : 0;
    unsigned m = __ballot_sync(0xffffffffu, bad);
    __shared__ unsigned s[4];
    if ((tid & 31) == 0) s[tid >> 5] = m;
    __syncthreads();
    if (tid == 0) g_is64 = ((s[0] | s[1] | s[2] | s[3]) == 0u) ? 1 : 0;
}

__global__ __launch_bounds__(256) void zero_int(int M) {
    int idx = blockIdx.x * blockDim.x + threadIdx.x;
    if (idx < M) g_degi[idx] = 0;
    else if (idx < 2 * M) g_cnt[idx - M] = 0;
}

// Decode edges into packed int2 {src,dst} + in-degree histogram.
__global__ __launch_bounds__(256) void decode_kernel(const void* __restrict__ ei,
                                                     int nE) {
    int e = blockIdx.x * blockDim.x + threadIdx.x;
    if (e >= nE) return;
    int src, dst;
    if (g_is64) {
        const long long* p = (const long long*)ei;
        src = (int)p[e];
        dst = (int)p[nE + e];
    } else {
        const int* p = (const int*)ei;
        src = p[e];
        dst = p[nE + e];
    }
    g_edge[e] = make_int2(src, dst);
    atomicAdd(&g_degi[dst], 1);
}

// ---------------------------------------------------------------------------
// Exclusive scan of g_degi -> g_rowstart (3 kernels, 256 elems/block).
// ---------------------------------------------------------------------------
__global__ __launch_bounds__(256) void scanA(int M) {
    __shared__ int s[256];
    int tid = threadIdx.x;
    int i = blockIdx.x * 256 + tid;
    int v = (i < M) ? g_degi[i] : 0;
    s[tid] = v;
    __syncthreads();
#pragma unroll
    for (int off = 1; off < 256; off <<= 1) {
        int t = (tid >= off) ? s[tid - off] : 0;
        __syncthreads();
        s[tid] += t;
        __syncthreads();
    }
    if (i < M) g_rowstart[i] = s[tid] - v;          // exclusive
    if (tid == 255) g_blocksums[blockIdx.x] = s[255];
}

__global__ void scanB(int nB) {
    __shared__ int s[512];
    int tid = threadIdx.x;
    int v = (tid < nB) ? g_blocksums[tid] : 0;
    s[tid] = v;
    __syncthreads();
#pragma unroll
    for (int off = 1; off < 512; off <<= 1) {
        int t = (tid >= off) ? s[tid - off] : 0;
        __syncthreads();
        s[tid] += t;
        __syncthreads();
    }
    if (tid < nB) g_blocksums[tid] = s[tid] - v;    // exclusive
}

__global__ __launch_bounds__(256) void scanC(int M, int nE) {
    int i = blockIdx.x * 256 + threadIdx.x;
    if (i < M) g_rowstart[i] += g_blocksums[blockIdx.x];
    if (i == 0) g_rowstart[M] = nE;
}

__global__ __launch_bounds__(256) void csr_fill(int nE) {
    int e = blockIdx.x * blockDim.x + threadIdx.x;
    if (e >= nE) return;
    int2 ed = g_edge[e];
    int pos = g_rowstart[ed.y] + atomicAdd(&g_cnt[ed.y], 1);
    g_adj[pos] = ed.x;
}

// ---------------------------------------------------------------------------
// GEMM layer 1: Y[M][128] = X[M][128] @ [Wa(64x128); Wb(64x128)]^T
// BM=128, BN=128, BK=16, FFMA2 inner loop (unchanged from R8).
// ---------------------------------------------------------------------------
__global__ __launch_bounds__(256, 2) void gemm1(const float* __restrict__ X,
                                                const float* __restrict__ Wa,
                                                const float* __restrict__ Wb,
                                                int M) {
    __shared__ float Xs[16][132];
    __shared__ float Ws[16][132];

    const int tid = threadIdx.x;
    const int m0 = blockIdx.x * 128;
    const int tr = tid >> 4;
    const int tc = tid & 15;
    const int lrow = tid >> 2;
    const int lc4 = (tid & 3) * 4;

    ull acc[8][4];
#pragma unroll
    for (int i = 0; i < 8; i++)
#pragma unroll
        for (int j = 0; j < 4; j++) acc[i][j] = 0ull;

    for (int k0 = 0; k0 < 128; k0 += 16) {
#pragma unroll
        for (int s = 0; s < 2; s++) {
            int r = lrow + s * 64;
            int gm = m0 + r;
            float4 v = make_float4(0.f, 0.f, 0.f, 0.f);
            if (gm < M) v = *(const float4*)&X[(size_t)gm * 128 + k0 + lc4];
            Xs[lc4 + 0][r] = v.x; Xs[lc4 + 1][r] = v.y;
            Xs[lc4 + 2][r] = v.z; Xs[lc4 + 3][r] = v.w;
        }
#pragma unroll
        for (int s = 0; s < 2; s++) {
            int n = lrow + s * 64;
            const float* w = (n < 64) ? (Wa + (size_t)n * 128)
                                      : (Wb + (size_t)(n - 64) * 128);
            float4 v = *(const float4*)&w[k0 + lc4];
            Ws[lc4 + 0][n] = v.x; Ws[lc4 + 1][n] = v.y;
            Ws[lc4 + 2][n] = v.z; Ws[lc4 + 3][n] = v.w;
        }
        __syncthreads();

#pragma unroll
        for (int kk = 0; kk < 16; kk++) {
            float4 xa = *(const float4*)&Xs[kk][tr * 4];
            float4 xb = *(const float4*)&Xs[kk][64 + tr * 4];
            float4 wa = *(const float4*)&Ws[kk][tc * 4];
            float4 wb = *(const float4*)&Ws[kk][64 + tc * 4];
            ull wp[4] = {pack2(wa.x, wa.y), pack2(wa.z, wa.w),
                         pack2(wb.x, wb.y), pack2(wb.z, wb.w)};
            float xv[8] = {xa.x, xa.y, xa.z, xa.w, xb.x, xb.y, xb.z, xb.w};
#pragma unroll
            for (int i = 0; i < 8; i++) {
                ull xd = pack2(xv[i], xv[i]);
#pragma unroll
                for (int j = 0; j < 4; j++) fma2(acc[i][j], xd, wp[j]);
            }
        }
        __syncthreads();
    }

#pragma unroll
    for (int si = 0; si < 2; si++)
#pragma unroll
        for (int i = 0; i < 4; i++) {
            int m = m0 + si * 64 + tr * 4 + i;
            if (m < M) {
                int a = si * 4 + i;
#pragma unroll
                for (int sj = 0; sj < 2; sj++) {
                    float4 v;
                    unpack2(v.x, v.y, acc[a][sj * 2 + 0]);
                    unpack2(v.z, v.w, acc[a][sj * 2 + 1]);
                    *(float4*)&g_y1[(size_t)m * 128 + sj * 64 + tc * 4] = v;
                }
            }
        }
}

// ---------------------------------------------------------------------------
// GEMM layer 2: Y[M][64] = H[M][64] @ [Wa(32x64); Wb(32x64)]^T (R8 FFMA2).
// ---------------------------------------------------------------------------
__global__ __launch_bounds__(256, 2) void gemm2(const float* __restrict__ Wa,
                                                const float* __restrict__ Wb,
                                                int M) {
    __shared__ float Xs[16][132];
    __shared__ float Ws[16][68];

    const int tid = threadIdx.x;
    const int m0 = blockIdx.x * 128;
    const int tr = tid >> 4;
    const int tc = tid & 15;
    const int lrow = tid >> 2;
    const int lc4 = (tid & 3) * 4;

    ull acc[8][2];
#pragma unroll
    for (int i = 0; i < 8; i++) { acc[i][0] = 0ull; acc[i][1] = 0ull; }

    for (int k0 = 0; k0 < 64; k0 += 16) {
#pragma unroll
        for (int s = 0; s < 2; s++) {
            int r = lrow + s * 64;
            int gm = m0 + r;
            float4 v = make_float4(0.f, 0.f, 0.f, 0.f);
            if (gm < M) v = *(const float4*)&g_h[(size_t)gm * 64 + k0 + lc4];
            Xs[lc4 + 0][r] = v.x; Xs[lc4 + 1][r] = v.y;
            Xs[lc4 + 2][r] = v.z; Xs[lc4 + 3][r] = v.w;
        }
        {
            int n = lrow;
            const float* w = (n < 32) ? (Wa + (size_t)n * 64)
                                      : (Wb + (size_t)(n - 32) * 64);
            float4 v = *(const float4*)&w[k0 + lc4];
            Ws[lc4 + 0][n] = v.x; Ws[lc4 + 1][n] = v.y;
            Ws[lc4 + 2][n] = v.z; Ws[lc4 + 3][n] = v.w;
        }
        __syncthreads();

#pragma unroll
        for (int kk = 0; kk < 16; kk++) {
            float4 xa = *(const float4*)&Xs[kk][tr * 4];
            float4 xb = *(const float4*)&Xs[kk][64 + tr * 4];
            float4 wa = *(const float4*)&Ws[kk][tc * 4];
            ull wp[2] = {pack2(wa.x, wa.y), pack2(wa.z, wa.w)};
            float xv[8] = {xa.x, xa.y, xa.z, xa.w, xb.x, xb.y, xb.z, xb.w};
#pragma unroll
            for (int i = 0; i < 8; i++) {
                ull xd = pack2(xv[i], xv[i]);
                fma2(acc[i][0], xd, wp[0]);
                fma2(acc[i][1], xd, wp[1]);
            }
        }
        __syncthreads();
    }

#pragma unroll
    for (int si = 0; si < 2; si++)
#pragma unroll
        for (int i = 0; i < 4; i++) {
            int m = m0 + si * 64 + tr * 4 + i;
            if (m < M) {
                int a = si * 4 + i;
                float4 v;
                unpack2(v.x, v.y, acc[a][0]);
                unpack2(v.z, v.w, acc[a][1]);
                *(float4*)&g_y2[(size_t)m * 64 + tc * 4] = v;
            }
        }
}

// ---------------------------------------------------------------------------
// gather1: warp per dst. lanes = 16 cols x 2 neighbors. Fuses combine:
//   h[dst] = relu(mean + b1 + y1[dst, 64:128])
// ---------------------------------------------------------------------------
__global__ __launch_bounds__(256) void gather1(const float4* __restrict__ b1,
                                               int M) {
    int w = (blockIdx.x * blockDim.x + threadIdx.x) >> 5;
    if (w >= M) return;
    int lane = threadIdx.x & 31;
    int c = lane & 15;
    int n = lane >> 4;
    int beg = g_rowstart[w];
    int end = g_rowstart[w + 1];

    float4 acc = make_float4(0.f, 0.f, 0.f, 0.f);
    for (int j = beg + n; j < end; j += 2) {
        int src = __ldg(&g_adj[j]);
        float4 v = __ldg((const float4*)g_y1 + (size_t)src * 32 + c);
        acc.x += v.x; acc.y += v.y; acc.z += v.z; acc.w += v.w;
    }
    acc.x += __shfl_down_sync(0xffffffffu, acc.x, 16);
    acc.y += __shfl_down_sync(0xffffffffu, acc.y, 16);
    acc.z += __shfl_down_sync(0xffffffffu, acc.z, 16);
    acc.w += __shfl_down_sync(0xffffffffu, acc.w, 16);

    if (n == 0) {
        float inv = 1.0f / fmaxf((float)(end - beg), 1.0f);
        float4 r = __ldg((const float4*)g_y1 + (size_t)w * 32 + 16 + c);
        float4 b = __ldg(&b1[c]);
        float4 o;
        o.x = fmaxf(fmaf(acc.x, inv, b.x + r.x), 0.f);
        o.y = fmaxf(fmaf(acc.y, inv, b.y + r.y), 0.f);
        o.z = fmaxf(fmaf(acc.z, inv, b.z + r.z), 0.f);
        o.w = fmaxf(fmaf(acc.w, inv, b.w + r.w), 0.f);
        ((float4*)g_h)[(size_t)w * 16 + c] = o;
    }
}

// ---------------------------------------------------------------------------
// gather2: warp per dst. lanes = 8 cols x 4 neighbors. Fuses final:
//   out[dst] = mean + b2 + y2[dst, 32:64]
// ---------------------------------------------------------------------------
__global__ __launch_bounds__(256) void gather2(const float4* __restrict__ b2,
                                               float* __restrict__ out, int M) {
    int w = (blockIdx.x * blockDim.x + threadIdx.x) >> 5;
    if (w >= M) return;
    int lane = threadIdx.x & 31;
    int c = lane & 7;
    int n = lane >> 3;
    int beg = g_rowstart[w];
    int end = g_rowstart[w + 1];

    float4 acc = make_float4(0.f, 0.f, 0.f, 0.f);
    for (int j = beg + n; j < end; j += 4) {
        int src = __ldg(&g_adj[j]);
        float4 v = __ldg((const float4*)g_y2 + (size_t)src * 16 + c);
        acc.x += v.x; acc.y += v.y; acc.z += v.z; acc.w += v.w;
    }
    acc.x += __shfl_down_sync(0xffffffffu, acc.x, 16);
    acc.y += __shfl_down_sync(0xffffffffu, acc.y, 16);
    acc.z += __shfl_down_sync(0xffffffffu, acc.z, 16);
    acc.w += __shfl_down_sync(0xffffffffu, acc.w, 16);
    acc.x += __shfl_down_sync(0xffffffffu, acc.x, 8);
    acc.y += __shfl_down_sync(0xffffffffu, acc.y, 8);
    acc.z += __shfl_down_sync(0xffffffffu, acc.z, 8);
    acc.w += __shfl_down_sync(0xffffffffu, acc.w, 8);

    if (n == 0) {
        float inv = 1.0f / fmaxf((float)(end - beg), 1.0f);
        float4 r = __ldg((const float4*)g_y2 + (size_t)w * 16 + 8 + c);
        float4 b = __ldg(&b2[c]);
        float4 o;
        o.x = fmaf(acc.x, inv, b.x + r.x);
        o.y = fmaf(acc.y, inv, b.y + r.y);
        o.z = fmaf(acc.z, inv, b.z + r.z);
        o.w = fmaf(acc.w, inv, b.w + r.w);
        ((float4*)out)[(size_t)w * 8 + c] = o;
    }
}

// ---------------------------------------------------------------------------
static inline int cdiv(int a, int b) { return (a + b - 1) / b; }

extern "C" void kernel_launch(void* const* d_in, const int* in_sizes, int n_in,
                              void* d_out, int out_size) {
    const float* x    = (const float*)d_in[0];
    const void*  ei   = d_in[1];
    const float* W1l  = (const float*)d_in[2];
    const float* b1   = (const float*)d_in[3];
    const float* W1r  = (const float*)d_in[4];
    const float* W2l  = (const float*)d_in[5];
    const float* b2   = (const float*)d_in[6];
    const float* W2r  = (const float*)d_in[7];
    float* out = (float*)d_out;

    const int M  = in_sizes[0] / DIN;   // 100000
    const int nE = in_sizes[1] / 2;     // 1600000
    const int nB = cdiv(M, 256);        // scan blocks (<=512 required)

    detect_kernel<<<1, 128>>>((const int*)ei, nE);
    zero_int<<<cdiv(2 * M, 256), 256>>>(M);
    decode_kernel<<<cdiv(nE, 256), 256>>>(ei, nE);
    scanA<<<nB, 256>>>(M);
    scanB<<<1, 512>>>(nB);
    scanC<<<nB, 256>>>(M, nE);
    csr_fill<<<cdiv(nE, 256), 256>>>(nE);
    gemm1<<<cdiv(M, 128), 256>>>(x, W1l, W1r, M);
    gather1<<<cdiv(M * 32, 256), 256>>>((const float4*)b1, M);
    gemm2<<<cdiv(M, 128), 256>>>(W2l, W2r, M);
    gather2<<<cdiv(M * 32, 256), 256>>>((const float4*)b2, out, M);
}

// round 10
// speedup vs baseline: 1.6471x; 1.2189x over previous
#include <cuda_runtime.h>
#include <cstdint>

// GraphSAGE 2-layer, mean aggregation. Transform-then-aggregate + CSR-gather.
//   y1 = x @ [W1_l; W1_r]^T        (tf32 mma.sync tensor-core GEMM)
//   h  = relu(gather-mean(y1[:,0:64]) + b1 + y1[:,64:128])
//   y2 = h @ [W2_l; W2_r]^T        (tf32 mma)
//   out= gather-mean(y2[:,0:32]) + b2 + y2[:,32:64]
// tf32 input rounding gives ~1e-4 rel err (budget 1e-3).

#define MAXN 100000
#define MAXE 1600000
#define DIN 128
#define DH 64
#define DOUT 32

__device__ __align__(16) float g_y1[MAXN * (2 * DH)];   // [M][128]
__device__ __align__(16) float g_h[MAXN * DH];          // [M][64]
__device__ __align__(16) float g_y2[MAXN * (2 * DOUT)]; // [M][64]
__device__ __align__(16) int2  g_edge[MAXE];
__device__ __align__(16) int   g_adj[MAXE];             // CSR adjacency (src)
__device__ __align__(16) int   g_rowstart[MAXN + 1];
__device__ __align__(16) int   g_degi[MAXN];
__device__ __align__(16) int   g_cnt[MAXN];
__device__ __align__(16) int   g_blocksums[512];
__device__ int g_is64;

// ---------------------------------------------------------------------------
__device__ __forceinline__ unsigned f2tf(float f) {
    unsigned r;
    asm("cvt.rna.tf32.f32 %0, %1;" : "=r"(r) : "f"(f));
    return r;
}
__device__ __forceinline__ void mma_tf32(float* c, const unsigned* a,
                                         const unsigned* b) {
    asm volatile(
        "mma.sync.aligned.m16n8k8.row.col.f32.tf32.tf32.f32 "
        "{%0,%1,%2,%3}, {%4,%5,%6,%7}, {%8,%9}, {%0,%1,%2,%3};"
        : "+f"(c[0]), "+f"(c[1]), "+f"(c[2]), "+f"(c[3])
        : "r"(a[0]), "r"(a[1]), "r"(a[2]), "r"(a[3]), "r"(b[0]), "r"(b[1]));
}

// ---------------------------------------------------------------------------
__global__ void detect_kernel(const int* __restrict__ ei32, int nE) {
    int n = nE < 128 ? nE : 128;
    int tid = threadIdx.x;
    int bad = (tid < n && ei32[2 * tid + 1] != 0) ? 1 : 0;
    unsigned m = __ballot_sync(0xffffffffu, bad);
    __shared__ unsigned s[4];
    if ((tid & 31) == 0) s[tid >> 5] = m;
    __syncthreads();
    if (tid == 0) g_is64 = ((s[0] | s[1] | s[2] | s[3]) == 0u) ? 1 : 0;
}

__global__ __launch_bounds__(256) void zero_int(int M) {
    int idx = blockIdx.x * blockDim.x + threadIdx.x;
    if (idx < M) g_degi[idx] = 0;
    else if (idx < 2 * M) g_cnt[idx - M] = 0;
}

__global__ __launch_bounds__(256) void decode_kernel(const void* __restrict__ ei,
                                                     int nE) {
    int e = blockIdx.x * blockDim.x + threadIdx.x;
    if (e >= nE) return;
    int src, dst;
    if (g_is64) {
        const long long* p = (const long long*)ei;
        src = (int)p[e];
        dst = (int)p[nE + e];
    } else {
        const int* p = (const int*)ei;
        src = p[e];
        dst = p[nE + e];
    }
    g_edge[e] = make_int2(src, dst);
    atomicAdd(&g_degi[dst], 1);
}

// ---------------------------------------------------------------------------
// Exclusive scan of g_degi -> g_rowstart
// ---------------------------------------------------------------------------
__global__ __launch_bounds__(256) void scanA(int M) {
    __shared__ int s[256];
    int tid = threadIdx.x;
    int i = blockIdx.x * 256 + tid;
    int v = (i < M) ? g_degi[i] : 0;
    s[tid] = v;
    __syncthreads();
#pragma unroll
    for (int off = 1; off < 256; off <<= 1) {
        int t = (tid >= off) ? s[tid - off] : 0;
        __syncthreads();
        s[tid] += t;
        __syncthreads();
    }
    if (i < M) g_rowstart[i] = s[tid] - v;
    if (tid == 255) g_blocksums[blockIdx.x] = s[255];
}

__global__ void scanB(int nB) {
    __shared__ int s[512];
    int tid = threadIdx.x;
    int v = (tid < nB) ? g_blocksums[tid] : 0;
    s[tid] = v;
    __syncthreads();
#pragma unroll
    for (int off = 1; off < 512; off <<= 1) {
        int t = (tid >= off) ? s[tid - off] : 0;
        __syncthreads();
        s[tid] += t;
        __syncthreads();
    }
    if (tid < nB) g_blocksums[tid] = s[tid] - v;
}

__global__ __launch_bounds__(256) void scanC(int M, int nE) {
    int i = blockIdx.x * 256 + threadIdx.x;
    if (i < M) g_rowstart[i] += g_blocksums[blockIdx.x];
    if (i == 0) g_rowstart[M] = nE;
}

__global__ __launch_bounds__(256) void csr_fill(int nE) {
    int e = blockIdx.x * blockDim.x + threadIdx.x;
    if (e >= nE) return;
    int2 ed = g_edge[e];
    int pos = g_rowstart[ed.y] + atomicAdd(&g_cnt[ed.y], 1);
    g_adj[pos] = ed.x;
}

// ---------------------------------------------------------------------------
// GEMM1 (tf32 tensor cores): Y[M][128] = X[M][128] @ [Wa; Wb]^T
// BM=128, BN=128, BK=32. 8 warps, warp tile 64x32 (4 M-tiles x 4 N-tiles of
// m16n8k8). Inputs cvt'd to tf32 during smem fill. Padded stride 36 words.
// ---------------------------------------------------------------------------
__global__ __launch_bounds__(256) void gemm1(const float* __restrict__ X,
                                             const float* __restrict__ Wa,
                                             const float* __restrict__ Wb,
                                             int M) {
    __shared__ unsigned As[128 * 36];
    __shared__ unsigned Bs[128 * 36];

    const int tid = threadIdx.x;
    const int lane = tid & 31;
    const int warp = tid >> 5;
    const int wm = (warp & 1) * 64;     // warp M offset
    const int wn = (warp >> 1) * 32;    // warp N offset
    const int m0 = blockIdx.x * 128;

    const int lr = tid >> 1;            // load row 0..127
    const int lcbase = (tid & 1) * 16;  // 0 or 16

    float acc[4][4][4];                 // [mt][nt][frag]
#pragma unroll
    for (int a = 0; a < 4; a++)
#pragma unroll
        for (int b = 0; b < 4; b++)
#pragma unroll
            for (int f = 0; f < 4; f++) acc[a][b][f] = 0.f;

    for (int k0 = 0; k0 < 128; k0 += 32) {
        // A tile: rows m0..m0+127, cols k0..k0+31
        {
            int gm = m0 + lr;
#pragma unroll
            for (int i = 0; i < 4; i++) {
                int c = lcbase + i * 4;
                float4 v = make_float4(0.f, 0.f, 0.f, 0.f);
                if (gm < M) v = *(const float4*)&X[(size_t)gm * 128 + k0 + c];
                uint4 t = make_uint4(f2tf(v.x), f2tf(v.y), f2tf(v.z), f2tf(v.w));
                *(uint4*)&As[lr * 36 + c] = t;
            }
        }
        // B tile: output cols (n) 0..127, cols k0..k0+31
        {
            const float* w = (lr < 64) ? (Wa + (size_t)lr * 128)
                                       : (Wb + (size_t)(lr - 64) * 128);
#pragma unroll
            for (int i = 0; i < 4; i++) {
                int c = lcbase + i * 4;
                float4 v = *(const float4*)&w[k0 + c];
                uint4 t = make_uint4(f2tf(v.x), f2tf(v.y), f2tf(v.z), f2tf(v.w));
                *(uint4*)&Bs[lr * 36 + c] = t;
            }
        }
        __syncthreads();

#pragma unroll
        for (int ks = 0; ks < 4; ks++) {
            const int kc = ks * 8;
            unsigned af[4][4], bf[4][2];
#pragma unroll
            for (int mt = 0; mt < 4; mt++) {
                int r = wm + mt * 16 + (lane >> 2);
                int c = kc + (lane & 3);
                af[mt][0] = As[r * 36 + c];
                af[mt][1] = As[(r + 8) * 36 + c];
                af[mt][2] = As[r * 36 + c + 4];
                af[mt][3] = As[(r + 8) * 36 + c + 4];
            }
#pragma unroll
            for (int nt = 0; nt < 4; nt++) {
                int n = wn + nt * 8 + (lane >> 2);
                bf[nt][0] = Bs[n * 36 + kc + (lane & 3)];
                bf[nt][1] = Bs[n * 36 + kc + 4 + (lane & 3)];
            }
#pragma unroll
            for (int mt = 0; mt < 4; mt++)
#pragma unroll
                for (int nt = 0; nt < 4; nt++)
                    mma_tf32(acc[mt][nt], af[mt], bf[nt]);
        }
        __syncthreads();
    }

    // Epilogue: c0,c1 -> (row, col..col+1); c2,c3 -> (row+8, ...)
#pragma unroll
    for (int mt = 0; mt < 4; mt++) {
#pragma unroll
        for (int nt = 0; nt < 4; nt++) {
            int row = m0 + wm + mt * 16 + (lane >> 2);
            int col = wn + nt * 8 + (lane & 3) * 2;
            if (row < M)
                *(float2*)&g_y1[(size_t)row * 128 + col] =
                    make_float2(acc[mt][nt][0], acc[mt][nt][1]);
            if (row + 8 < M)
                *(float2*)&g_y1[(size_t)(row + 8) * 128 + col] =
                    make_float2(acc[mt][nt][2], acc[mt][nt][3]);
        }
    }
}

// ---------------------------------------------------------------------------
// GEMM2 (tf32): Y[M][64] = H[M][64] @ [Wa(32x64); Wb(32x64)]^T
// BM=128, BN=64, BK=32 (2 chunks). warp tile 64x16 (4 M x 2 N).
// ---------------------------------------------------------------------------
__global__ __launch_bounds__(256) void gemm2(const float* __restrict__ Wa,
                                             const float* __restrict__ Wb,
                                             int M) {
    __shared__ unsigned As[128 * 36];
    __shared__ unsigned Bs[64 * 36];

    const int tid = threadIdx.x;
    const int lane = tid & 31;
    const int warp = tid >> 5;
    const int wm = (warp & 1) * 64;
    const int wn = (warp >> 1) * 16;
    const int m0 = blockIdx.x * 128;

    const int lr = tid >> 1;
    const int lcbase = (tid & 1) * 16;

    float acc[4][2][4];
#pragma unroll
    for (int a = 0; a < 4; a++)
#pragma unroll
        for (int b = 0; b < 2; b++)
#pragma unroll
            for (int f = 0; f < 4; f++) acc[a][b][f] = 0.f;

    for (int k0 = 0; k0 < 64; k0 += 32) {
        {
            int gm = m0 + lr;
#pragma unroll
            for (int i = 0; i < 4; i++) {
                int c = lcbase + i * 4;
                float4 v = make_float4(0.f, 0.f, 0.f, 0.f);
                if (gm < M) v = *(const float4*)&g_h[(size_t)gm * 64 + k0 + c];
                uint4 t = make_uint4(f2tf(v.x), f2tf(v.y), f2tf(v.z), f2tf(v.w));
                *(uint4*)&As[lr * 36 + c] = t;
            }
        }
        // B tile: 64 n-rows x 32 k. Threads 0..127 load it (lr<64).
        if (lr < 64) {
            const float* w = (lr < 32) ? (Wa + (size_t)lr * 64)
                                       : (Wb + (size_t)(lr - 32) * 64);
#pragma unroll
            for (int i = 0; i < 4; i++) {
                int c = lcbase + i * 4;
                float4 v = *(const float4*)&w[k0 + c];
                uint4 t = make_uint4(f2tf(v.x), f2tf(v.y), f2tf(v.z), f2tf(v.w));
                *(uint4*)&Bs[lr * 36 + c] = t;
            }
        }
        __syncthreads();

#pragma unroll
        for (int ks = 0; ks < 4; ks++) {
            const int kc = ks * 8;
            unsigned af[4][4], bf[2][2];
#pragma unroll
            for (int mt = 0; mt < 4; mt++) {
                int r = wm + mt * 16 + (lane >> 2);
                int c = kc + (lane & 3);
                af[mt][0] = As[r * 36 + c];
                af[mt][1] = As[(r + 8) * 36 + c];
                af[mt][2] = As[r * 36 + c + 4];
                af[mt][3] = As[(r + 8) * 36 + c + 4];
            }
#pragma unroll
            for (int nt = 0; nt < 2; nt++) {
                int n = wn + nt * 8 + (lane >> 2);
                bf[nt][0] = Bs[n * 36 + kc + (lane & 3)];
                bf[nt][1] = Bs[n * 36 + kc + 4 + (lane & 3)];
            }
#pragma unroll
            for (int mt = 0; mt < 4; mt++)
#pragma unroll
                for (int nt = 0; nt < 2; nt++)
                    mma_tf32(acc[mt][nt], af[mt], bf[nt]);
        }
        __syncthreads();
    }

#pragma unroll
    for (int mt = 0; mt < 4; mt++) {
#pragma unroll
        for (int nt = 0; nt < 2; nt++) {
            int row = m0 + wm + mt * 16 + (lane >> 2);
            int col = wn + nt * 8 + (lane & 3) * 2;
            if (row < M)
                *(float2*)&g_y2[(size_t)row * 64 + col] =
                    make_float2(acc[mt][nt][0], acc[mt][nt][1]);
            if (row + 8 < M)
                *(float2*)&g_y2[(size_t)(row + 8) * 64 + col] =
                    make_float2(acc[mt][nt][2], acc[mt][nt][3]);
        }
    }
}

// ---------------------------------------------------------------------------
// gather1: warp per dst. lanes = 16 cols x 2 neighbors. Fuses combine:
//   h[dst] = relu(mean + b1 + y1[dst, 64:128])
// ---------------------------------------------------------------------------
__global__ __launch_bounds__(256) void gather1(const float4* __restrict__ b1,
                                               int M) {
    int w = (blockIdx.x * blockDim.x + threadIdx.x) >> 5;
    if (w >= M) return;
    int lane = threadIdx.x & 31;
    int c = lane & 15;
    int n = lane >> 4;
    int beg = g_rowstart[w];
    int end = g_rowstart[w + 1];

    float4 acc = make_float4(0.f, 0.f, 0.f, 0.f);
    for (int j = beg + n; j < end; j += 2) {
        int src = __ldg(&g_adj[j]);
        float4 v = __ldg((const float4*)g_y1 + (size_t)src * 32 + c);
        acc.x += v.x; acc.y += v.y; acc.z += v.z; acc.w += v.w;
    }
    acc.x += __shfl_down_sync(0xffffffffu, acc.x, 16);
    acc.y += __shfl_down_sync(0xffffffffu, acc.y, 16);
    acc.z += __shfl_down_sync(0xffffffffu, acc.z, 16);
    acc.w += __shfl_down_sync(0xffffffffu, acc.w, 16);

    if (n == 0) {
        float inv = 1.0f / fmaxf((float)(end - beg), 1.0f);
        float4 r = __ldg((const float4*)g_y1 + (size_t)w * 32 + 16 + c);
        float4 b = __ldg(&b1[c]);
        float4 o;
        o.x = fmaxf(fmaf(acc.x, inv, b.x + r.x), 0.f);
        o.y = fmaxf(fmaf(acc.y, inv, b.y + r.y), 0.f);
        o.z = fmaxf(fmaf(acc.z, inv, b.z + r.z), 0.f);
        o.w = fmaxf(fmaf(acc.w, inv, b.w + r.w), 0.f);
        ((float4*)g_h)[(size_t)w * 16 + c] = o;
    }
}

// ---------------------------------------------------------------------------
// gather2: warp per dst. lanes = 8 cols x 4 neighbors. Fuses final:
//   out[dst] = mean + b2 + y2[dst, 32:64]
// ---------------------------------------------------------------------------
__global__ __launch_bounds__(256) void gather2(const float4* __restrict__ b2,
                                               float* __restrict__ out, int M) {
    int w = (blockIdx.x * blockDim.x + threadIdx.x) >> 5;
    if (w >= M) return;
    int lane = threadIdx.x & 31;
    int c = lane & 7;
    int n = lane >> 3;
    int beg = g_rowstart[w];
    int end = g_rowstart[w + 1];

    float4 acc = make_float4(0.f, 0.f, 0.f, 0.f);
    for (int j = beg + n; j < end; j += 4) {
        int src = __ldg(&g_adj[j]);
        float4 v = __ldg((const float4*)g_y2 + (size_t)src * 16 + c);
        acc.x += v.x; acc.y += v.y; acc.z += v.z; acc.w += v.w;
    }
    acc.x += __shfl_down_sync(0xffffffffu, acc.x, 16);
    acc.y += __shfl_down_sync(0xffffffffu, acc.y, 16);
    acc.z += __shfl_down_sync(0xffffffffu, acc.z, 16);
    acc.w += __shfl_down_sync(0xffffffffu, acc.w, 16);
    acc.x += __shfl_down_sync(0xffffffffu, acc.x, 8);
    acc.y += __shfl_down_sync(0xffffffffu, acc.y, 8);
    acc.z += __shfl_down_sync(0xffffffffu, acc.z, 8);
    acc.w += __shfl_down_sync(0xffffffffu, acc.w, 8);

    if (n == 0) {
        float inv = 1.0f / fmaxf((float)(end - beg), 1.0f);
        float4 r = __ldg((const float4*)g_y2 + (size_t)w * 16 + 8 + c);
        float4 b = __ldg(&b2[c]);
        float4 o;
        o.x = fmaf(acc.x, inv, b.x + r.x);
        o.y = fmaf(acc.y, inv, b.y + r.y);
        o.z = fmaf(acc.z, inv, b.z + r.z);
        o.w = fmaf(acc.w, inv, b.w + r.w);
        ((float4*)out)[(size_t)w * 8 + c] = o;
    }
}

// ---------------------------------------------------------------------------
static inline int cdiv(int a, int b) { return (a + b - 1) / b; }

extern "C" void kernel_launch(void* const* d_in, const int* in_sizes, int n_in,
                              void* d_out, int out_size) {
    const float* x    = (const float*)d_in[0];
    const void*  ei   = d_in[1];
    const float* W1l  = (const float*)d_in[2];
    const float* b1   = (const float*)d_in[3];
    const float* W1r  = (const float*)d_in[4];
    const float* W2l  = (const float*)d_in[5];
    const float* b2   = (const float*)d_in[6];
    const float* W2r  = (const float*)d_in[7];
    float* out = (float*)d_out;

    const int M  = in_sizes[0] / DIN;   // 100000
    const int nE = in_sizes[1] / 2;     // 1600000
    const int nB = cdiv(M, 256);

    detect_kernel<<<1, 128>>>((const int*)ei, nE);
    zero_int<<<cdiv(2 * M, 256), 256>>>(M);
    decode_kernel<<<cdiv(nE, 256), 256>>>(ei, nE);
    scanA<<<nB, 256>>>(M);
    scanB<<<1, 512>>>(nB);
    scanC<<<nB, 256>>>(M, nE);
    csr_fill<<<cdiv(nE, 256), 256>>>(nE);
    gemm1<<<cdiv(M, 128), 256>>>(x, W1l, W1r, M);
    gather1<<<cdiv(M * 32, 256), 256>>>((const float4*)b1, M);
    gemm2<<<cdiv(M, 128), 256>>>(W2l, W2r, M);
    gather2<<<cdiv(M * 32, 256), 256>>>((const float4*)b2, out, M);
}

// round 11
// speedup vs baseline: 1.7675x; 1.0731x over previous
#include <cuda_runtime.h>
#include <cstdint>

// GraphSAGE 2-layer, mean aggregation. Transform-then-aggregate + CSR-gather.
//   y1 = x @ [W1_l; W1_r]^T        (tf32 mma.sync tensor-core GEMM)
//   h  = relu(gather-mean(y1[:,0:64]) + b1 + y1[:,64:128])
//   y2 = h @ [W2_l; W2_r]^T        (tf32 mma)
//   out= gather-mean(y2[:,0:32]) + b2 + y2[:,32:64]
// CSR build (stream2) runs concurrently with gemm1 (stream0); fork/join via
// events inside graph capture. tf32 => rel_err ~3.7e-4 (budget 1e-3).

#define MAXN 100000
#define MAXE 1600000
#define DIN 128
#define DH 64
#define DOUT 32

__device__ __align__(16) float g_y1[MAXN * (2 * DH)];   // [M][128]
__device__ __align__(16) float g_h[MAXN * DH];          // [M][64]
__device__ __align__(16) float g_y2[MAXN * (2 * DOUT)]; // [M][64]
__device__ __align__(16) int   g_adj[MAXE];             // CSR adjacency (src)
__device__ __align__(16) int   g_rowstart[MAXN + 1];
__device__ __align__(16) int   g_degi[MAXN];
__device__ __align__(16) int   g_cnt[MAXN];
__device__ __align__(16) int   g_blocksums[512];
__device__ int g_is64;

// ---------------------------------------------------------------------------
__device__ __forceinline__ unsigned f2tf(float f) {
    unsigned r;
    asm("cvt.rna.tf32.f32 %0, %1;" : "=r"(r) : "f"(f));
    return r;
}
__device__ __forceinline__ void mma_tf32(float* c, const unsigned* a,
                                         const unsigned* b) {
    asm volatile(
        "mma.sync.aligned.m16n8k8.row.col.f32.tf32.tf32.f32 "
        "{%0,%1,%2,%3}, {%4,%5,%6,%7}, {%8,%9}, {%0,%1,%2,%3};"
        : "+f"(c[0]), "+f"(c[1]), "+f"(c[2]), "+f"(c[3])
        : "r"(a[0]), "r"(a[1]), "r"(a[2]), "r"(a[3]), "r"(b[0]), "r"(b[1]));
}

// ---------------------------------------------------------------------------
__global__ void detect_kernel(const int* __restrict__ ei32, int nE) {
    int n = nE < 128 ? nE : 128;
    int tid = threadIdx.x;
    int bad = (tid < n && ei32[2 * tid + 1] != 0) ? 1 : 0;
    unsigned m = __ballot_sync(0xffffffffu, bad);
    __shared__ unsigned s[4];
    if ((tid & 31) == 0) s[tid >> 5] = m;
    __syncthreads();
    if (tid == 0) g_is64 = ((s[0] | s[1] | s[2] | s[3]) == 0u) ? 1 : 0;
}

__global__ __launch_bounds__(256) void zero_int(int M) {
    int idx = blockIdx.x * blockDim.x + threadIdx.x;
    if (idx < M) g_degi[idx] = 0;
    else if (idx < 2 * M) g_cnt[idx - M] = 0;
}

// Histogram only: read dst half of edge buffer.
__global__ __launch_bounds__(256) void decode_kernel(const void* __restrict__ ei,
                                                     int nE) {
    int e = blockIdx.x * blockDim.x + threadIdx.x;
    if (e >= nE) return;
    int dst;
    if (g_is64) dst = (int)((const long long*)ei)[nE + e];
    else        dst = ((const int*)ei)[nE + e];
    atomicAdd(&g_degi[dst], 1);
}

// ---------------------------------------------------------------------------
// Exclusive scan of g_degi -> g_rowstart
// ---------------------------------------------------------------------------
__global__ __launch_bounds__(256) void scanA(int M) {
    __shared__ int s[256];
    int tid = threadIdx.x;
    int i = blockIdx.x * 256 + tid;
    int v = (i < M) ? g_degi[i] : 0;
    s[tid] = v;
    __syncthreads();
#pragma unroll
    for (int off = 1; off < 256; off <<= 1) {
        int t = (tid >= off) ? s[tid - off] : 0;
        __syncthreads();
        s[tid] += t;
        __syncthreads();
    }
    if (i < M) g_rowstart[i] = s[tid] - v;
    if (tid == 255) g_blocksums[blockIdx.x] = s[255];
}

__global__ void scanB(int nB) {
    __shared__ int s[512];
    int tid = threadIdx.x;
    int v = (tid < nB) ? g_blocksums[tid] : 0;
    s[tid] = v;
    __syncthreads();
#pragma unroll
    for (int off = 1; off < 512; off <<= 1) {
        int t = (tid >= off) ? s[tid - off] : 0;
        __syncthreads();
        s[tid] += t;
        __syncthreads();
    }
    if (tid < nB) g_blocksums[tid] = s[tid] - v;
}

__global__ __launch_bounds__(256) void scanC(int M, int nE) {
    int i = blockIdx.x * 256 + threadIdx.x;
    if (i < M) g_rowstart[i] += g_blocksums[blockIdx.x];
    if (i == 0) g_rowstart[M] = nE;
}

// Fill CSR directly from raw edge buffer.
__global__ __launch_bounds__(256) void csr_fill(const void* __restrict__ ei,
                                                int nE) {
    int e = blockIdx.x * blockDim.x + threadIdx.x;
    if (e >= nE) return;
    int src, dst;
    if (g_is64) {
        const long long* p = (const long long*)ei;
        src = (int)p[e];
        dst = (int)p[nE + e];
    } else {
        const int* p = (const int*)ei;
        src = p[e];
        dst = p[nE + e];
    }
    int pos = g_rowstart[dst] + atomicAdd(&g_cnt[dst], 1);
    g_adj[pos] = src;
}

// ---------------------------------------------------------------------------
// GEMM1 (tf32 tensor cores): Y[M][128] = X[M][128] @ [Wa; Wb]^T
// BM=128, BN=128, BK=32. 8 warps, warp tile 64x32. Padded stride 36 words.
// ---------------------------------------------------------------------------
__global__ __launch_bounds__(256) void gemm1(const float* __restrict__ X,
                                             const float* __restrict__ Wa,
                                             const float* __restrict__ Wb,
                                             int M) {
    __shared__ unsigned As[128 * 36];
    __shared__ unsigned Bs[128 * 36];

    const int tid = threadIdx.x;
    const int lane = tid & 31;
    const int warp = tid >> 5;
    const int wm = (warp & 1) * 64;
    const int wn = (warp >> 1) * 32;
    const int m0 = blockIdx.x * 128;

    const int lr = tid >> 1;
    const int lcbase = (tid & 1) * 16;

    float acc[4][4][4];
#pragma unroll
    for (int a = 0; a < 4; a++)
#pragma unroll
        for (int b = 0; b < 4; b++)
#pragma unroll
            for (int f = 0; f < 4; f++) acc[a][b][f] = 0.f;

    for (int k0 = 0; k0 < 128; k0 += 32) {
        {
            int gm = m0 + lr;
#pragma unroll
            for (int i = 0; i < 4; i++) {
                int c = lcbase + i * 4;
                float4 v = make_float4(0.f, 0.f, 0.f, 0.f);
                if (gm < M) v = *(const float4*)&X[(size_t)gm * 128 + k0 + c];
                uint4 t = make_uint4(f2tf(v.x), f2tf(v.y), f2tf(v.z), f2tf(v.w));
                *(uint4*)&As[lr * 36 + c] = t;
            }
        }
        {
            const float* w = (lr < 64) ? (Wa + (size_t)lr * 128)
                                       : (Wb + (size_t)(lr - 64) * 128);
#pragma unroll
            for (int i = 0; i < 4; i++) {
                int c = lcbase + i * 4;
                float4 v = *(const float4*)&w[k0 + c];
                uint4 t = make_uint4(f2tf(v.x), f2tf(v.y), f2tf(v.z), f2tf(v.w));
                *(uint4*)&Bs[lr * 36 + c] = t;
            }
        }
        __syncthreads();

#pragma unroll
        for (int ks = 0; ks < 4; ks++) {
            const int kc = ks * 8;
            unsigned af[4][4], bf[4][2];
#pragma unroll
            for (int mt = 0; mt < 4; mt++) {
                int r = wm + mt * 16 + (lane >> 2);
                int c = kc + (lane & 3);
                af[mt][0] = As[r * 36 + c];
                af[mt][1] = As[(r + 8) * 36 + c];
                af[mt][2] = As[r * 36 + c + 4];
                af[mt][3] = As[(r + 8) * 36 + c + 4];
            }
#pragma unroll
            for (int nt = 0; nt < 4; nt++) {
                int n = wn + nt * 8 + (lane >> 2);
                bf[nt][0] = Bs[n * 36 + kc + (lane & 3)];
                bf[nt][1] = Bs[n * 36 + kc + 4 + (lane & 3)];
            }
#pragma unroll
            for (int mt = 0; mt < 4; mt++)
#pragma unroll
                for (int nt = 0; nt < 4; nt++)
                    mma_tf32(acc[mt][nt], af[mt], bf[nt]);
        }
        __syncthreads();
    }

#pragma unroll
    for (int mt = 0; mt < 4; mt++) {
#pragma unroll
        for (int nt = 0; nt < 4; nt++) {
            int row = m0 + wm + mt * 16 + (lane >> 2);
            int col = wn + nt * 8 + (lane & 3) * 2;
            if (row < M)
                *(float2*)&g_y1[(size_t)row * 128 + col] =
                    make_float2(acc[mt][nt][0], acc[mt][nt][1]);
            if (row + 8 < M)
                *(float2*)&g_y1[(size_t)(row + 8) * 128 + col] =
                    make_float2(acc[mt][nt][2], acc[mt][nt][3]);
        }
    }
}

// ---------------------------------------------------------------------------
// GEMM2 (tf32): Y[M][64] = H[M][64] @ [Wa(32x64); Wb(32x64)]^T
// ---------------------------------------------------------------------------
__global__ __launch_bounds__(256) void gemm2(const float* __restrict__ Wa,
                                             const float* __restrict__ Wb,
                                             int M) {
    __shared__ unsigned As[128 * 36];
    __shared__ unsigned Bs[64 * 36];

    const int tid = threadIdx.x;
    const int lane = tid & 31;
    const int warp = tid >> 5;
    const int wm = (warp & 1) * 64;
    const int wn = (warp >> 1) * 16;
    const int m0 = blockIdx.x * 128;

    const int lr = tid >> 1;
    const int lcbase = (tid & 1) * 16;

    float acc[4][2][4];
#pragma unroll
    for (int a = 0; a < 4; a++)
#pragma unroll
        for (int b = 0; b < 2; b++)
#pragma unroll
            for (int f = 0; f < 4; f++) acc[a][b][f] = 0.f;

    for (int k0 = 0; k0 < 64; k0 += 32) {
        {
            int gm = m0 + lr;
#pragma unroll
            for (int i = 0; i < 4; i++) {
                int c = lcbase + i * 4;
                float4 v = make_float4(0.f, 0.f, 0.f, 0.f);
                if (gm < M) v = *(const float4*)&g_h[(size_t)gm * 64 + k0 + c];
                uint4 t = make_uint4(f2tf(v.x), f2tf(v.y), f2tf(v.z), f2tf(v.w));
                *(uint4*)&As[lr * 36 + c] = t;
            }
        }
        if (lr < 64) {
            const float* w = (lr < 32) ? (Wa + (size_t)lr * 64)
                                       : (Wb + (size_t)(lr - 32) * 64);
#pragma unroll
            for (int i = 0; i < 4; i++) {
                int c = lcbase + i * 4;
                float4 v = *(const float4*)&w[k0 + c];
                uint4 t = make_uint4(f2tf(v.x), f2tf(v.y), f2tf(v.z), f2tf(v.w));
                *(uint4*)&Bs[lr * 36 + c] = t;
            }
        }
        __syncthreads();

#pragma unroll
        for (int ks = 0; ks < 4; ks++) {
            const int kc = ks * 8;
            unsigned af[4][4], bf[2][2];
#pragma unroll
            for (int mt = 0; mt < 4; mt++) {
                int r = wm + mt * 16 + (lane >> 2);
                int c = kc + (lane & 3);
                af[mt][0] = As[r * 36 + c];
                af[mt][1] = As[(r + 8) * 36 + c];
                af[mt][2] = As[r * 36 + c + 4];
                af[mt][3] = As[(r + 8) * 36 + c + 4];
            }
#pragma unroll
            for (int nt = 0; nt < 2; nt++) {
                int n = wn + nt * 8 + (lane >> 2);
                bf[nt][0] = Bs[n * 36 + kc + (lane & 3)];
                bf[nt][1] = Bs[n * 36 + kc + 4 + (lane & 3)];
            }
#pragma unroll
            for (int mt = 0; mt < 4; mt++)
#pragma unroll
                for (int nt = 0; nt < 2; nt++)
                    mma_tf32(acc[mt][nt], af[mt], bf[nt]);
        }
        __syncthreads();
    }

#pragma unroll
    for (int mt = 0; mt < 4; mt++) {
#pragma unroll
        for (int nt = 0; nt < 2; nt++) {
            int row = m0 + wm + mt * 16 + (lane >> 2);
            int col = wn + nt * 8 + (lane & 3) * 2;
            if (row < M)
                *(float2*)&g_y2[(size_t)row * 64 + col] =
                    make_float2(acc[mt][nt][0], acc[mt][nt][1]);
            if (row + 8 < M)
                *(float2*)&g_y2[(size_t)(row + 8) * 64 + col] =
                    make_float2(acc[mt][nt][2], acc[mt][nt][3]);
        }
    }
}

// ---------------------------------------------------------------------------
// gather1: warp per dst. lanes = 16 cols x 2 neighbors. Fuses combine:
//   h[dst] = relu(mean + b1 + y1[dst, 64:128])
// ---------------------------------------------------------------------------
__global__ __launch_bounds__(256) void gather1(const float4* __restrict__ b1,
                                               int M) {
    int w = (blockIdx.x * blockDim.x + threadIdx.x) >> 5;
    if (w >= M) return;
    int lane = threadIdx.x & 31;
    int c = lane & 15;
    int n = lane >> 4;
    int beg = g_rowstart[w];
    int end = g_rowstart[w + 1];

    float4 acc = make_float4(0.f, 0.f, 0.f, 0.f);
    for (int j = beg + n; j < end; j += 2) {
        int src = __ldg(&g_adj[j]);
        float4 v = __ldg((const float4*)g_y1 + (size_t)src * 32 + c);
        acc.x += v.x; acc.y += v.y; acc.z += v.z; acc.w += v.w;
    }
    acc.x += __shfl_down_sync(0xffffffffu, acc.x, 16);
    acc.y += __shfl_down_sync(0xffffffffu, acc.y, 16);
    acc.z += __shfl_down_sync(0xffffffffu, acc.z, 16);
    acc.w += __shfl_down_sync(0xffffffffu, acc.w, 16);

    if (n == 0) {
        float inv = 1.0f / fmaxf((float)(end - beg), 1.0f);
        float4 r = __ldg((const float4*)g_y1 + (size_t)w * 32 + 16 + c);
        float4 b = __ldg(&b1[c]);
        float4 o;
        o.x = fmaxf(fmaf(acc.x, inv, b.x + r.x), 0.f);
        o.y = fmaxf(fmaf(acc.y, inv, b.y + r.y), 0.f);
        o.z = fmaxf(fmaf(acc.z, inv, b.z + r.z), 0.f);
        o.w = fmaxf(fmaf(acc.w, inv, b.w + r.w), 0.f);
        ((float4*)g_h)[(size_t)w * 16 + c] = o;
    }
}

// ---------------------------------------------------------------------------
// gather2: warp per dst. lanes = 8 cols x 4 neighbors. Fuses final:
//   out[dst] = mean + b2 + y2[dst, 32:64]
// ---------------------------------------------------------------------------
__global__ __launch_bounds__(256) void gather2(const float4* __restrict__ b2,
                                               float* __restrict__ out, int M) {
    int w = (blockIdx.x * blockDim.x + threadIdx.x) >> 5;
    if (w >= M) return;
    int lane = threadIdx.x & 31;
    int c = lane & 7;
    int n = lane >> 3;
    int beg = g_rowstart[w];
    int end = g_rowstart[w + 1];

    float4 acc = make_float4(0.f, 0.f, 0.f, 0.f);
    for (int j = beg + n; j < end; j += 4) {
        int src = __ldg(&g_adj[j]);
        float4 v = __ldg((const float4*)g_y2 + (size_t)src * 16 + c);
        acc.x += v.x; acc.y += v.y; acc.z += v.z; acc.w += v.w;
    }
    acc.x += __shfl_down_sync(0xffffffffu, acc.x, 16);
    acc.y += __shfl_down_sync(0xffffffffu, acc.y, 16);
    acc.z += __shfl_down_sync(0xffffffffu, acc.z, 16);
    acc.w += __shfl_down_sync(0xffffffffu, acc.w, 16);
    acc.x += __shfl_down_sync(0xffffffffu, acc.x, 8);
    acc.y += __shfl_down_sync(0xffffffffu, acc.y, 8);
    acc.z += __shfl_down_sync(0xffffffffu, acc.z, 8);
    acc.w += __shfl_down_sync(0xffffffffu, acc.w, 8);

    if (n == 0) {
        float inv = 1.0f / fmaxf((float)(end - beg), 1.0f);
        float4 r = __ldg((const float4*)g_y2 + (size_t)w * 16 + 8 + c);
        float4 b = __ldg(&b2[c]);
        float4 o;
        o.x = fmaf(acc.x, inv, b.x + r.x);
        o.y = fmaf(acc.y, inv, b.y + r.y);
        o.z = fmaf(acc.z, inv, b.z + r.z);
        o.w = fmaf(acc.w, inv, b.w + r.w);
        ((float4*)out)[(size_t)w * 8 + c] = o;
    }
}

// ---------------------------------------------------------------------------
static inline int cdiv(int a, int b) { return (a + b - 1) / b; }

extern "C" void kernel_launch(void* const* d_in, const int* in_sizes, int n_in,
                              void* d_out, int out_size) {
    const float* x    = (const float*)d_in[0];
    const void*  ei   = d_in[1];
    const float* W1l  = (const float*)d_in[2];
    const float* b1   = (const float*)d_in[3];
    const float* W1r  = (const float*)d_in[4];
    const float* W2l  = (const float*)d_in[5];
    const float* b2   = (const float*)d_in[6];
    const float* W2r  = (const float*)d_in[7];
    float* out = (float*)d_out;

    const int M  = in_sizes[0] / DIN;   // 100000
    const int nE = in_sizes[1] / 2;     // 1600000
    const int nB = cdiv(M, 256);

    // Lazily-created side stream + fork/join events (host resources, created
    // once; no device memory involved).
    static cudaStream_t s2 = nullptr;
    static cudaEvent_t evFork = nullptr, evJoin = nullptr;
    if (s2 == nullptr) {
        cudaStreamCreateWithFlags(&s2, cudaStreamNonBlocking);
        cudaEventCreateWithFlags(&evFork, cudaEventDisableTiming);
        cudaEventCreateWithFlags(&evJoin, cudaEventDisableTiming);
    }

    // Fork: CSR build on s2, gemm1 on default stream (both only read inputs).
    cudaEventRecord(evFork, 0);
    cudaStreamWaitEvent(s2, evFork, 0);

    detect_kernel<<<1, 128, 0, s2>>>((const int*)ei, nE);
    zero_int<<<cdiv(2 * M, 256), 256, 0, s2>>>(M);
    decode_kernel<<<cdiv(nE, 256), 256, 0, s2>>>(ei, nE);
    scanA<<<nB, 256, 0, s2>>>(M);
    scanB<<<1, 512, 0, s2>>>(nB);
    scanC<<<nB, 256, 0, s2>>>(M, nE);
    csr_fill<<<cdiv(nE, 256), 256, 0, s2>>>(ei, nE);

    gemm1<<<cdiv(M, 128), 256>>>(x, W1l, W1r, M);

    // Join: gather1 needs both CSR (s2) and y1 (stream 0).
    cudaEventRecord(evJoin, s2);
    cudaStreamWaitEvent(0, evJoin, 0);

    gather1<<<cdiv(M * 32, 256), 256>>>((const float4*)b1, M);
    gemm2<<<cdiv(M, 128), 256>>>(W2l, W2r, M);
    gather2<<<cdiv(M * 32, 256), 256>>>((const float4*)b2, out, M);
}

// round 12
// speedup vs baseline: 1.7856x; 1.0102x over previous
#include <cuda_runtime.h>
#include <cuda_fp16.h>
#include <cstdint>

// GraphSAGE 2-layer, mean aggregation. Transform-then-aggregate + CSR-gather.
//   y1 = x @ [W1_l; W1_r]^T   (tf32 mma; agg half stored fp16, root half fp32)
//   h  = relu(gather-mean(y1agg) + b1 + y1root)
//   y2 = h @ [W2_l; W2_r]^T   (tf32 mma; same fp16/fp32 split)
//   out= gather-mean(y2agg) + b2 + y2root
// fp16 edge payload halves gather L2 traffic; fp16 eps (2^-11) == tf32 eps,
// so combined rel_err ~5e-4 vs 1e-3 budget. CSR build overlaps gemm1 (streams).

#define MAXN 100000
#define MAXE 1600000
#define DIN 128
#define DH 64
#define DOUT 32

__device__ __align__(16) __half g_y1agg[MAXN * DH];      // [M][64] fp16
__device__ __align__(16) float  g_y1root[MAXN * DH];     // [M][64] fp32
__device__ __align__(16) float  g_h[MAXN * DH];          // [M][64]
__device__ __align__(16) __half g_y2agg[MAXN * DOUT];    // [M][32] fp16
__device__ __align__(16) float  g_y2root[MAXN * DOUT];   // [M][32] fp32
__device__ __align__(16) int    g_adj[MAXE];
__device__ __align__(16) int    g_rowstart[MAXN + 1];
__device__ __align__(16) int    g_degi[MAXN];
__device__ __align__(16) int    g_cnt[MAXN];
__device__ __align__(16) int    g_blocksums[512];
__device__ int g_is64;

// ---------------------------------------------------------------------------
__device__ __forceinline__ unsigned f2tf(float f) {
    unsigned r;
    asm("cvt.rna.tf32.f32 %0, %1;" : "=r"(r) : "f"(f));
    return r;
}
__device__ __forceinline__ void mma_tf32(float* c, const unsigned* a,
                                         const unsigned* b) {
    asm volatile(
        "mma.sync.aligned.m16n8k8.row.col.f32.tf32.tf32.f32 "
        "{%0,%1,%2,%3}, {%4,%5,%6,%7}, {%8,%9}, {%0,%1,%2,%3};"
        : "+f"(c[0]), "+f"(c[1]), "+f"(c[2]), "+f"(c[3])
        : "r"(a[0]), "r"(a[1]), "r"(a[2]), "r"(a[3]), "r"(b[0]), "r"(b[1]));
}
__device__ __forceinline__ void acc8(float* a, uint4 v) {
    float2 f0 = __half22float2(*(__half2*)&v.x);
    float2 f1 = __half22float2(*(__half2*)&v.y);
    float2 f2 = __half22float2(*(__half2*)&v.z);
    float2 f3 = __half22float2(*(__half2*)&v.w);
    a[0] += f0.x; a[1] += f0.y; a[2] += f1.x; a[3] += f1.y;
    a[4] += f2.x; a[5] += f2.y; a[6] += f3.x; a[7] += f3.y;
}

// ---------------------------------------------------------------------------
__global__ void detect_kernel(const int* __restrict__ ei32, int nE) {
    int n = nE < 128 ? nE : 128;
    int tid = threadIdx.x;
    int bad = (tid < n && ei32[2 * tid + 1] != 0) ? 1 : 0;
    unsigned m = __ballot_sync(0xffffffffu, bad);
    __shared__ unsigned s[4];
    if ((tid & 31) == 0) s[tid >> 5] = m;
    __syncthreads();
    if (tid == 0) g_is64 = ((s[0] | s[1] | s[2] | s[3]) == 0u) ? 1 : 0;
}

__global__ __launch_bounds__(256) void zero_int(int M) {
    int idx = blockIdx.x * blockDim.x + threadIdx.x;
    if (idx < M) g_degi[idx] = 0;
    else if (idx < 2 * M) g_cnt[idx - M] = 0;
}

__global__ __launch_bounds__(256) void decode_kernel(const void* __restrict__ ei,
                                                     int nE) {
    int e = blockIdx.x * blockDim.x + threadIdx.x;
    if (e >= nE) return;
    int dst;
    if (g_is64) dst = (int)((const long long*)ei)[nE + e];
    else        dst = ((const int*)ei)[nE + e];
    atomicAdd(&g_degi[dst], 1);
}

__global__ __launch_bounds__(256) void scanA(int M) {
    __shared__ int s[256];
    int tid = threadIdx.x;
    int i = blockIdx.x * 256 + tid;
    int v = (i < M) ? g_degi[i] : 0;
    s[tid] = v;
    __syncthreads();
#pragma unroll
    for (int off = 1; off < 256; off <<= 1) {
        int t = (tid >= off) ? s[tid - off] : 0;
        __syncthreads();
        s[tid] += t;
        __syncthreads();
    }
    if (i < M) g_rowstart[i] = s[tid] - v;
    if (tid == 255) g_blocksums[blockIdx.x] = s[255];
}

__global__ void scanB(int nB) {
    __shared__ int s[512];
    int tid = threadIdx.x;
    int v = (tid < nB) ? g_blocksums[tid] : 0;
    s[tid] = v;
    __syncthreads();
#pragma unroll
    for (int off = 1; off < 512; off <<= 1) {
        int t = (tid >= off) ? s[tid - off] : 0;
        __syncthreads();
        s[tid] += t;
        __syncthreads();
    }
    if (tid < nB) g_blocksums[tid] = s[tid] - v;
}

__global__ __launch_bounds__(256) void scanC(int M, int nE) {
    int i = blockIdx.x * 256 + threadIdx.x;
    if (i < M) g_rowstart[i] += g_blocksums[blockIdx.x];
    if (i == 0) g_rowstart[M] = nE;
}

__global__ __launch_bounds__(256) void csr_fill(const void* __restrict__ ei,
                                                int nE) {
    int e = blockIdx.x * blockDim.x + threadIdx.x;
    if (e >= nE) return;
    int src, dst;
    if (g_is64) {
        const long long* p = (const long long*)ei;
        src = (int)p[e];
        dst = (int)p[nE + e];
    } else {
        const int* p = (const int*)ei;
        src = p[e];
        dst = p[nE + e];
    }
    int pos = g_rowstart[dst] + atomicAdd(&g_cnt[dst], 1);
    g_adj[pos] = src;
}

// ---------------------------------------------------------------------------
// GEMM1 (tf32): [y1agg(fp16) | y1root(fp32)] = X @ [Wa; Wb]^T
// BM=128, BN=128, BK=32, 8 warps, warp tile 64x32, padded stride 36.
// ---------------------------------------------------------------------------
__global__ __launch_bounds__(256) void gemm1(const float* __restrict__ X,
                                             const float* __restrict__ Wa,
                                             const float* __restrict__ Wb,
                                             int M) {
    __shared__ unsigned As[128 * 36];
    __shared__ unsigned Bs[128 * 36];

    const int tid = threadIdx.x;
    const int lane = tid & 31;
    const int warp = tid >> 5;
    const int wm = (warp & 1) * 64;
    const int wn = (warp >> 1) * 32;
    const int m0 = blockIdx.x * 128;

    const int lr = tid >> 1;
    const int lcbase = (tid & 1) * 16;

    float acc[4][4][4];
#pragma unroll
    for (int a = 0; a < 4; a++)
#pragma unroll
        for (int b = 0; b < 4; b++)
#pragma unroll
            for (int f = 0; f < 4; f++) acc[a][b][f] = 0.f;

    for (int k0 = 0; k0 < 128; k0 += 32) {
        {
            int gm = m0 + lr;
#pragma unroll
            for (int i = 0; i < 4; i++) {
                int c = lcbase + i * 4;
                float4 v = make_float4(0.f, 0.f, 0.f, 0.f);
                if (gm < M) v = *(const float4*)&X[(size_t)gm * 128 + k0 + c];
                uint4 t = make_uint4(f2tf(v.x), f2tf(v.y), f2tf(v.z), f2tf(v.w));
                *(uint4*)&As[lr * 36 + c] = t;
            }
        }
        {
            const float* w = (lr < 64) ? (Wa + (size_t)lr * 128)
                                       : (Wb + (size_t)(lr - 64) * 128);
#pragma unroll
            for (int i = 0; i < 4; i++) {
                int c = lcbase + i * 4;
                float4 v = *(const float4*)&w[k0 + c];
                uint4 t = make_uint4(f2tf(v.x), f2tf(v.y), f2tf(v.z), f2tf(v.w));
                *(uint4*)&Bs[lr * 36 + c] = t;
            }
        }
        __syncthreads();

#pragma unroll
        for (int ks = 0; ks < 4; ks++) {
            const int kc = ks * 8;
            unsigned af[4][4], bf[4][2];
#pragma unroll
            for (int mt = 0; mt < 4; mt++) {
                int r = wm + mt * 16 + (lane >> 2);
                int c = kc + (lane & 3);
                af[mt][0] = As[r * 36 + c];
                af[mt][1] = As[(r + 8) * 36 + c];
                af[mt][2] = As[r * 36 + c + 4];
                af[mt][3] = As[(r + 8) * 36 + c + 4];
            }
#pragma unroll
            for (int nt = 0; nt < 4; nt++) {
                int n = wn + nt * 8 + (lane >> 2);
                bf[nt][0] = Bs[n * 36 + kc + (lane & 3)];
                bf[nt][1] = Bs[n * 36 + kc + 4 + (lane & 3)];
            }
#pragma unroll
            for (int mt = 0; mt < 4; mt++)
#pragma unroll
                for (int nt = 0; nt < 4; nt++)
                    mma_tf32(acc[mt][nt], af[mt], bf[nt]);
        }
        __syncthreads();
    }

#pragma unroll
    for (int mt = 0; mt < 4; mt++) {
#pragma unroll
        for (int nt = 0; nt < 4; nt++) {
            int row = m0 + wm + mt * 16 + (lane >> 2);
            int col = wn + nt * 8 + (lane & 3) * 2;
            if (col < 64) {   // agg half -> fp16
                __half2 h0 = __floats2half2_rn(acc[mt][nt][0], acc[mt][nt][1]);
                __half2 h1 = __floats2half2_rn(acc[mt][nt][2], acc[mt][nt][3]);
                if (row < M)
                    *(__half2*)&g_y1agg[(size_t)row * 64 + col] = h0;
                if (row + 8 < M)
                    *(__half2*)&g_y1agg[(size_t)(row + 8) * 64 + col] = h1;
            } else {          // root half -> fp32
                int rc = col - 64;
                if (row < M)
                    *(float2*)&g_y1root[(size_t)row * 64 + rc] =
                        make_float2(acc[mt][nt][0], acc[mt][nt][1]);
                if (row + 8 < M)
                    *(float2*)&g_y1root[(size_t)(row + 8) * 64 + rc] =
                        make_float2(acc[mt][nt][2], acc[mt][nt][3]);
            }
        }
    }
}

// ---------------------------------------------------------------------------
// GEMM2 (tf32): [y2agg(fp16) | y2root(fp32)] = H @ [Wa; Wb]^T
// ---------------------------------------------------------------------------
__global__ __launch_bounds__(256) void gemm2(const float* __restrict__ Wa,
                                             const float* __restrict__ Wb,
                                             int M) {
    __shared__ unsigned As[128 * 36];
    __shared__ unsigned Bs[64 * 36];

    const int tid = threadIdx.x;
    const int lane = tid & 31;
    const int warp = tid >> 5;
    const int wm = (warp & 1) * 64;
    const int wn = (warp >> 1) * 16;
    const int m0 = blockIdx.x * 128;

    const int lr = tid >> 1;
    const int lcbase = (tid & 1) * 16;

    float acc[4][2][4];
#pragma unroll
    for (int a = 0; a < 4; a++)
#pragma unroll
        for (int b = 0; b < 2; b++)
#pragma unroll
            for (int f = 0; f < 4; f++) acc[a][b][f] = 0.f;

    for (int k0 = 0; k0 < 64; k0 += 32) {
        {
            int gm = m0 + lr;
#pragma unroll
            for (int i = 0; i < 4; i++) {
                int c = lcbase + i * 4;
                float4 v = make_float4(0.f, 0.f, 0.f, 0.f);
                if (gm < M) v = *(const float4*)&g_h[(size_t)gm * 64 + k0 + c];
                uint4 t = make_uint4(f2tf(v.x), f2tf(v.y), f2tf(v.z), f2tf(v.w));
                *(uint4*)&As[lr * 36 + c] = t;
            }
        }
        if (lr < 64) {
            const float* w = (lr < 32) ? (Wa + (size_t)lr * 64)
                                       : (Wb + (size_t)(lr - 32) * 64);
#pragma unroll
            for (int i = 0; i < 4; i++) {
                int c = lcbase + i * 4;
                float4 v = *(const float4*)&w[k0 + c];
                uint4 t = make_uint4(f2tf(v.x), f2tf(v.y), f2tf(v.z), f2tf(v.w));
                *(uint4*)&Bs[lr * 36 + c] = t;
            }
        }
        __syncthreads();

#pragma unroll
        for (int ks = 0; ks < 4; ks++) {
            const int kc = ks * 8;
            unsigned af[4][4], bf[2][2];
#pragma unroll
            for (int mt = 0; mt < 4; mt++) {
                int r = wm + mt * 16 + (lane >> 2);
                int c = kc + (lane & 3);
                af[mt][0] = As[r * 36 + c];
                af[mt][1] = As[(r + 8) * 36 + c];
                af[mt][2] = As[r * 36 + c + 4];
                af[mt][3] = As[(r + 8) * 36 + c + 4];
            }
#pragma unroll
            for (int nt = 0; nt < 2; nt++) {
                int n = wn + nt * 8 + (lane >> 2);
                bf[nt][0] = Bs[n * 36 + kc + (lane & 3)];
                bf[nt][1] = Bs[n * 36 + kc + 4 + (lane & 3)];
            }
#pragma unroll
            for (int mt = 0; mt < 4; mt++)
#pragma unroll
                for (int nt = 0; nt < 2; nt++)
                    mma_tf32(acc[mt][nt], af[mt], bf[nt]);
        }
        __syncthreads();
    }

#pragma unroll
    for (int mt = 0; mt < 4; mt++) {
#pragma unroll
        for (int nt = 0; nt < 2; nt++) {
            int row = m0 + wm + mt * 16 + (lane >> 2);
            int col = wn + nt * 8 + (lane & 3) * 2;
            if (col < 32) {   // agg half -> fp16
                __half2 h0 = __floats2half2_rn(acc[mt][nt][0], acc[mt][nt][1]);
                __half2 h1 = __floats2half2_rn(acc[mt][nt][2], acc[mt][nt][3]);
                if (row < M)
                    *(__half2*)&g_y2agg[(size_t)row * 32 + col] = h0;
                if (row + 8 < M)
                    *(__half2*)&g_y2agg[(size_t)(row + 8) * 32 + col] = h1;
            } else {          // root half -> fp32
                int rc = col - 32;
                if (row < M)
                    *(float2*)&g_y2root[(size_t)row * 32 + rc] =
                        make_float2(acc[mt][nt][0], acc[mt][nt][1]);
                if (row + 8 < M)
                    *(float2*)&g_y2root[(size_t)(row + 8) * 32 + rc] =
                        make_float2(acc[mt][nt][2], acc[mt][nt][3]);
            }
        }
    }
}

// ---------------------------------------------------------------------------
// gather1: warp per dst. Row = 64 fp16 = 128B = 8 uint4.
// Lane = (col-group c8 in 0..7) x (neighbor slot ns in 0..3). fp32 accumulate.
//   h[dst] = relu(mean + b1 + y1root[dst])
// ---------------------------------------------------------------------------
__global__ __launch_bounds__(256) void gather1(const float4* __restrict__ b1,
                                               int M) {
    int w = (blockIdx.x * blockDim.x + threadIdx.x) >> 5;
    if (w >= M) return;
    int lane = threadIdx.x & 31;
    int c8 = lane & 7;
    int ns = lane >> 3;
    int beg = g_rowstart[w];
    int end = g_rowstart[w + 1];

    float a[8] = {0.f, 0.f, 0.f, 0.f, 0.f, 0.f, 0.f, 0.f};
    for (int j = beg + ns; j < end; j += 4) {
        int src = __ldg(&g_adj[j]);
        uint4 v = __ldg((const uint4*)g_y1agg + (size_t)src * 8 + c8);
        acc8(a, v);
    }
#pragma unroll
    for (int i = 0; i < 8; i++) {
        a[i] += __shfl_down_sync(0xffffffffu, a[i], 16);
        a[i] += __shfl_down_sync(0xffffffffu, a[i], 8);
    }

    if (ns == 0) {
        float inv = 1.0f / fmaxf((float)(end - beg), 1.0f);
        const float4* root = (const float4*)g_y1root + (size_t)w * 16 + c8 * 2;
        float4 r0 = __ldg(root);
        float4 r1 = __ldg(root + 1);
        float4 b0 = __ldg(&b1[c8 * 2]);
        float4 b1v = __ldg(&b1[c8 * 2 + 1]);
        float4 o0, o1;
        o0.x = fmaxf(fmaf(a[0], inv, b0.x + r0.x), 0.f);
        o0.y = fmaxf(fmaf(a[1], inv, b0.y + r0.y), 0.f);
        o0.z = fmaxf(fmaf(a[2], inv, b0.z + r0.z), 0.f);
        o0.w = fmaxf(fmaf(a[3], inv, b0.w + r0.w), 0.f);
        o1.x = fmaxf(fmaf(a[4], inv, b1v.x + r1.x), 0.f);
        o1.y = fmaxf(fmaf(a[5], inv, b1v.y + r1.y), 0.f);
        o1.z = fmaxf(fmaf(a[6], inv, b1v.z + r1.z), 0.f);
        o1.w = fmaxf(fmaf(a[7], inv, b1v.w + r1.w), 0.f);
        float4* hp = (float4*)g_h + (size_t)w * 16 + c8 * 2;
        hp[0] = o0;
        hp[1] = o1;
    }
}

// ---------------------------------------------------------------------------
// gather2: warp per dst. Row = 32 fp16 = 64B = 4 uint4.
// Lane = (col-group c4 in 0..3) x (neighbor slot ns in 0..7).
//   out[dst] = mean + b2 + y2root[dst]
// ---------------------------------------------------------------------------
__global__ __launch_bounds__(256) void gather2(const float4* __restrict__ b2,
                                               float* __restrict__ out, int M) {
    int w = (blockIdx.x * blockDim.x + threadIdx.x) >> 5;
    if (w >= M) return;
    int lane = threadIdx.x & 31;
    int c4 = lane & 3;
    int ns = lane >> 2;
    int beg = g_rowstart[w];
    int end = g_rowstart[w + 1];

    float a[8] = {0.f, 0.f, 0.f, 0.f, 0.f, 0.f, 0.f, 0.f};
    for (int j = beg + ns; j < end; j += 8) {
        int src = __ldg(&g_adj[j]);
        uint4 v = __ldg((const uint4*)g_y2agg + (size_t)src * 4 + c4);
        acc8(a, v);
    }
#pragma unroll
    for (int i = 0; i < 8; i++) {
        a[i] += __shfl_down_sync(0xffffffffu, a[i], 16);
        a[i] += __shfl_down_sync(0xffffffffu, a[i], 8);
        a[i] += __shfl_down_sync(0xffffffffu, a[i], 4);
    }

    if (ns == 0) {
        float inv = 1.0f / fmaxf((float)(end - beg), 1.0f);
        const float4* root = (const float4*)g_y2root + (size_t)w * 8 + c4 * 2;
        float4 r0 = __ldg(root);
        float4 r1 = __ldg(root + 1);
        float4 b0 = __ldg(&b2[c4 * 2]);
        float4 b1v = __ldg(&b2[c4 * 2 + 1]);
        float4 o0, o1;
        o0.x = fmaf(a[0], inv, b0.x + r0.x);
        o0.y = fmaf(a[1], inv, b0.y + r0.y);
        o0.z = fmaf(a[2], inv, b0.z + r0.z);
        o0.w = fmaf(a[3], inv, b0.w + r0.w);
        o1.x = fmaf(a[4], inv, b1v.x + r1.x);
        o1.y = fmaf(a[5], inv, b1v.y + r1.y);
        o1.z = fmaf(a[6], inv, b1v.z + r1.z);
        o1.w = fmaf(a[7], inv, b1v.w + r1.w);
        float4* op = (float4*)out + (size_t)w * 8 + c4 * 2;
        op[0] = o0;
        op[1] = o1;
    }
}

// ---------------------------------------------------------------------------
static inline int cdiv(int a, int b) { return (a + b - 1) / b; }

extern "C" void kernel_launch(void* const* d_in, const int* in_sizes, int n_in,
                              void* d_out, int out_size) {
    const float* x    = (const float*)d_in[0];
    const void*  ei   = d_in[1];
    const float* W1l  = (const float*)d_in[2];
    const float* b1   = (const float*)d_in[3];
    const float* W1r  = (const float*)d_in[4];
    const float* W2l  = (const float*)d_in[5];
    const float* b2   = (const float*)d_in[6];
    const float* W2r  = (const float*)d_in[7];
    float* out = (float*)d_out;

    const int M  = in_sizes[0] / DIN;   // 100000
    const int nE = in_sizes[1] / 2;     // 1600000
    const int nB = cdiv(M, 256);

    static cudaStream_t s2 = nullptr;
    static cudaEvent_t evFork = nullptr, evJoin = nullptr;
    if (s2 == nullptr) {
        cudaStreamCreateWithFlags(&s2, cudaStreamNonBlocking);
        cudaEventCreateWithFlags(&evFork, cudaEventDisableTiming);
        cudaEventCreateWithFlags(&evJoin, cudaEventDisableTiming);
    }

    // Fork: CSR build on s2, gemm1 on default stream.
    cudaEventRecord(evFork, 0);
    cudaStreamWaitEvent(s2, evFork, 0);

    detect_kernel<<<1, 128, 0, s2>>>((const int*)ei, nE);
    zero_int<<<cdiv(2 * M, 256), 256, 0, s2>>>(M);
    decode_kernel<<<cdiv(nE, 256), 256, 0, s2>>>(ei, nE);
    scanA<<<nB, 256, 0, s2>>>(M);
    scanB<<<1, 512, 0, s2>>>(nB);
    scanC<<<nB, 256, 0, s2>>>(M, nE);
    csr_fill<<<cdiv(nE, 256), 256, 0, s2>>>(ei, nE);

    gemm1<<<cdiv(M, 128), 256>>>(x, W1l, W1r, M);

    // Join: gather1 needs CSR (s2) and y1 (stream 0).
    cudaEventRecord(evJoin, s2);
    cudaStreamWaitEvent(0, evJoin, 0);

    gather1<<<cdiv(M * 32, 256), 256>>>((const float4*)b1, M);
    gemm2<<<cdiv(M, 128), 256>>>(W2l, W2r, M);
    gather2<<<cdiv(M * 32, 256), 256>>>((const float4*)b2, out, M);
}

// round 13
// speedup vs baseline: 1.7876x; 1.0011x over previous
#include <cuda_runtime.h>
#include <cuda_fp16.h>
#include <cstdint>

// GraphSAGE 2-layer, mean aggregation. Transform-then-aggregate + CSR-gather.
//   y1 = x @ [W1_l; W1_r]^T   (tf32 mma; agg half fp16, root half fp32)
//   h  = relu(gather-mean(y1agg) + b1 + y1root)
//   y2 = h @ [W2_l; W2_r]^T
//   out= gather-mean(y2agg) + b2 + y2root
// CSR build overlaps gemm1. This round: CSR chain slimmed (vectorized decode/
// fill, countdown cursor instead of g_cnt, shuffle-based scans).

#define MAXN 100000
#define MAXE 1600000
#define DIN 128
#define DH 64
#define DOUT 32

__device__ __align__(16) __half g_y1agg[MAXN * DH];      // [M][64] fp16
__device__ __align__(16) float  g_y1root[MAXN * DH];     // [M][64] fp32
__device__ __align__(16) float  g_h[MAXN * DH];          // [M][64]
__device__ __align__(16) __half g_y2agg[MAXN * DOUT];    // [M][32] fp16
__device__ __align__(16) float  g_y2root[MAXN * DOUT];   // [M][32] fp32
__device__ __align__(16) int    g_adj[MAXE];
__device__ __align__(16) int    g_rowstart[MAXN + 1];
__device__ __align__(16) int    g_degi[MAXN];
__device__ __align__(16) int    g_blocksums[512];
__device__ int g_is64;

// ---------------------------------------------------------------------------
__device__ __forceinline__ unsigned f2tf(float f) {
    unsigned r;
    asm("cvt.rna.tf32.f32 %0, %1;" : "=r"(r) : "f"(f));
    return r;
}
__device__ __forceinline__ void mma_tf32(float* c, const unsigned* a,
                                         const unsigned* b) {
    asm volatile(
        "mma.sync.aligned.m16n8k8.row.col.f32.tf32.tf32.f32 "
        "{%0,%1,%2,%3}, {%4,%5,%6,%7}, {%8,%9}, {%0,%1,%2,%3};"
        : "+f"(c[0]), "+f"(c[1]), "+f"(c[2]), "+f"(c[3])
        : "r"(a[0]), "r"(a[1]), "r"(a[2]), "r"(a[3]), "r"(b[0]), "r"(b[1]));
}
__device__ __forceinline__ void acc8(float* a, uint4 v) {
    float2 f0 = __half22float2(*(__half2*)&v.x);
    float2 f1 = __half22float2(*(__half2*)&v.y);
    float2 f2 = __half22float2(*(__half2*)&v.z);
    float2 f3 = __half22float2(*(__half2*)&v.w);
    a[0] += f0.x; a[1] += f0.y; a[2] += f1.x; a[3] += f1.y;
    a[4] += f2.x; a[5] += f2.y; a[6] += f3.x; a[7] += f3.y;
}

// ---------------------------------------------------------------------------
__global__ void detect_kernel(const int* __restrict__ ei32, int nE) {
    int n = nE < 128 ? nE : 128;
    int tid = threadIdx.x;
    int bad = (tid < n && ei32[2 * tid + 1] != 0) ? 1 : 0;
    unsigned m = __ballot_sync(0xffffffffu, bad);
    __shared__ unsigned s[4];
    if ((tid & 31) == 0) s[tid >> 5] = m;
    __syncthreads();
    if (tid == 0) g_is64 = ((s[0] | s[1] | s[2] | s[3]) == 0u) ? 1 : 0;
}

__global__ __launch_bounds__(256) void zero_int(int M) {
    int idx = blockIdx.x * blockDim.x + threadIdx.x;
    if (idx < M) g_degi[idx] = 0;
}

// Histogram: 4 dsts per thread (vector int4 on the int32 path).
__global__ __launch_bounds__(256) void decode_kernel(const void* __restrict__ ei,
                                                     int nE) {
    int t = blockIdx.x * blockDim.x + threadIdx.x;
    int e0 = t * 4;
    if (e0 >= nE) return;
    if (g_is64) {
        const long long* p = (const long long*)ei + nE;
#pragma unroll
        for (int i = 0; i < 4; i++)
            if (e0 + i < nE) atomicAdd(&g_degi[(int)p[e0 + i]], 1);
    } else {
        const int* p = (const int*)ei + nE;
        if (e0 + 3 < nE) {
            int4 d = *(const int4*)&p[e0];
            atomicAdd(&g_degi[d.x], 1);
            atomicAdd(&g_degi[d.y], 1);
            atomicAdd(&g_degi[d.z], 1);
            atomicAdd(&g_degi[d.w], 1);
        } else {
            for (int i = 0; i < 4 && e0 + i < nE; i++)
                atomicAdd(&g_degi[p[e0 + i]], 1);
        }
    }
}

// ---------------------------------------------------------------------------
// Exclusive scan of g_degi -> g_rowstart: shuffle-based warp scans.
// ---------------------------------------------------------------------------
__global__ __launch_bounds__(256) void scanA(int M) {
    __shared__ int wsum[8];
    int tid = threadIdx.x;
    int lane = tid & 31;
    int warp = tid >> 5;
    int i = blockIdx.x * 256 + tid;
    int v = (i < M) ? g_degi[i] : 0;
    int x = v;
#pragma unroll
    for (int off = 1; off < 32; off <<= 1) {
        int t = __shfl_up_sync(0xffffffffu, x, off);
        if (lane >= off) x += t;
    }
    if (lane == 31) wsum[warp] = x;
    __syncthreads();
    if (warp == 0 && lane < 8) {
        int s = wsum[lane];
#pragma unroll
        for (int off = 1; off < 8; off <<= 1) {
            int t = __shfl_up_sync(0xffu, s, off, 8);
            if (lane >= off) s += t;
        }
        wsum[lane] = s;
    }
    __syncthreads();
    int base = (warp > 0) ? wsum[warp - 1] : 0;
    int incl = x + base;
    if (i < M) g_rowstart[i] = incl - v;            // exclusive
    if (tid == 255) g_blocksums[blockIdx.x] = incl; // block total
}

__global__ void scanB(int nB) {
    __shared__ int wsum[16];
    int tid = threadIdx.x;      // 512 threads
    int lane = tid & 31;
    int warp = tid >> 5;
    int v = (tid < nB) ? g_blocksums[tid] : 0;
    int x = v;
#pragma unroll
    for (int off = 1; off < 32; off <<= 1) {
        int t = __shfl_up_sync(0xffffffffu, x, off);
        if (lane >= off) x += t;
    }
    if (lane == 31) wsum[warp] = x;
    __syncthreads();
    if (warp == 0 && lane < 16) {
        int s = wsum[lane];
#pragma unroll
        for (int off = 1; off < 16; off <<= 1) {
            int t = __shfl_up_sync(0xffffu, s, off, 16);
            if (lane >= off) s += t;
        }
        wsum[lane] = s;
    }
    __syncthreads();
    int base = (warp > 0) ? wsum[warp - 1] : 0;
    if (tid < nB) g_blocksums[tid] = x + base - v;  // exclusive
}

__global__ __launch_bounds__(256) void scanC(int M, int nE) {
    int i = blockIdx.x * 256 + threadIdx.x;
    if (i < M) g_rowstart[i] += g_blocksums[blockIdx.x];
    if (i == 0) g_rowstart[M] = nE;
}

// Fill CSR: 4 edges per thread; countdown cursor in g_degi (no g_cnt).
__global__ __launch_bounds__(256) void csr_fill(const void* __restrict__ ei,
                                                int nE) {
    int t = blockIdx.x * blockDim.x + threadIdx.x;
    int e0 = t * 4;
    if (e0 >= nE) return;
    int src[4], dst[4], n = 0;
    if (g_is64) {
        const long long* ps = (const long long*)ei;
        const long long* pd = ps + nE;
        for (int i = 0; i < 4 && e0 + i < nE; i++) {
            src[i] = (int)ps[e0 + i];
            dst[i] = (int)pd[e0 + i];
            n++;
        }
    } else {
        const int* ps = (const int*)ei;
        const int* pd = ps + nE;
        if (e0 + 3 < nE) {
            int4 s4 = *(const int4*)&ps[e0];
            int4 d4 = *(const int4*)&pd[e0];
            src[0] = s4.x; src[1] = s4.y; src[2] = s4.z; src[3] = s4.w;
            dst[0] = d4.x; dst[1] = d4.y; dst[2] = d4.z; dst[3] = d4.w;
            n = 4;
        } else {
            for (int i = 0; i < 4 && e0 + i < nE; i++) {
                src[i] = ps[e0 + i];
                dst[i] = pd[e0 + i];
                n++;
            }
        }
    }
#pragma unroll
    for (int i = 0; i < 4; i++) {
        if (i < n) {
            int pos = g_rowstart[dst[i]] + atomicSub(&g_degi[dst[i]], 1) - 1;
            g_adj[pos] = src[i];
        }
    }
}

// ---------------------------------------------------------------------------
// GEMM1 (tf32): [y1agg(fp16) | y1root(fp32)] = X @ [Wa; Wb]^T
// ---------------------------------------------------------------------------
__global__ __launch_bounds__(256) void gemm1(const float* __restrict__ X,
                                             const float* __restrict__ Wa,
                                             const float* __restrict__ Wb,
                                             int M) {
    __shared__ unsigned As[128 * 36];
    __shared__ unsigned Bs[128 * 36];

    const int tid = threadIdx.x;
    const int lane = tid & 31;
    const int warp = tid >> 5;
    const int wm = (warp & 1) * 64;
    const int wn = (warp >> 1) * 32;
    const int m0 = blockIdx.x * 128;

    const int lr = tid >> 1;
    const int lcbase = (tid & 1) * 16;

    float acc[4][4][4];
#pragma unroll
    for (int a = 0; a < 4; a++)
#pragma unroll
        for (int b = 0; b < 4; b++)
#pragma unroll
            for (int f = 0; f < 4; f++) acc[a][b][f] = 0.f;

    for (int k0 = 0; k0 < 128; k0 += 32) {
        {
            int gm = m0 + lr;
#pragma unroll
            for (int i = 0; i < 4; i++) {
                int c = lcbase + i * 4;
                float4 v = make_float4(0.f, 0.f, 0.f, 0.f);
                if (gm < M) v = *(const float4*)&X[(size_t)gm * 128 + k0 + c];
                uint4 t = make_uint4(f2tf(v.x), f2tf(v.y), f2tf(v.z), f2tf(v.w));
                *(uint4*)&As[lr * 36 + c] = t;
            }
        }
        {
            const float* w = (lr < 64) ? (Wa + (size_t)lr * 128)
                                       : (Wb + (size_t)(lr - 64) * 128);
#pragma unroll
            for (int i = 0; i < 4; i++) {
                int c = lcbase + i * 4;
                float4 v = *(const float4*)&w[k0 + c];
                uint4 t = make_uint4(f2tf(v.x), f2tf(v.y), f2tf(v.z), f2tf(v.w));
                *(uint4*)&Bs[lr * 36 + c] = t;
            }
        }
        __syncthreads();

#pragma unroll
        for (int ks = 0; ks < 4; ks++) {
            const int kc = ks * 8;
            unsigned af[4][4], bf[4][2];
#pragma unroll
            for (int mt = 0; mt < 4; mt++) {
                int r = wm + mt * 16 + (lane >> 2);
                int c = kc + (lane & 3);
                af[mt][0] = As[r * 36 + c];
                af[mt][1] = As[(r + 8) * 36 + c];
                af[mt][2] = As[r * 36 + c + 4];
                af[mt][3] = As[(r + 8) * 36 + c + 4];
            }
#pragma unroll
            for (int nt = 0; nt < 4; nt++) {
                int n = wn + nt * 8 + (lane >> 2);
                bf[nt][0] = Bs[n * 36 + kc + (lane & 3)];
                bf[nt][1] = Bs[n * 36 + kc + 4 + (lane & 3)];
            }
#pragma unroll
            for (int mt = 0; mt < 4; mt++)
#pragma unroll
                for (int nt = 0; nt < 4; nt++)
                    mma_tf32(acc[mt][nt], af[mt], bf[nt]);
        }
        __syncthreads();
    }

#pragma unroll
    for (int mt = 0; mt < 4; mt++) {
#pragma unroll
        for (int nt = 0; nt < 4; nt++) {
            int row = m0 + wm + mt * 16 + (lane >> 2);
            int col = wn + nt * 8 + (lane & 3) * 2;
            if (col < 64) {
                __half2 h0 = __floats2half2_rn(acc[mt][nt][0], acc[mt][nt][1]);
                __half2 h1 = __floats2half2_rn(acc[mt][nt][2], acc[mt][nt][3]);
                if (row < M)
                    *(__half2*)&g_y1agg[(size_t)row * 64 + col] = h0;
                if (row + 8 < M)
                    *(__half2*)&g_y1agg[(size_t)(row + 8) * 64 + col] = h1;
            } else {
                int rc = col - 64;
                if (row < M)
                    *(float2*)&g_y1root[(size_t)row * 64 + rc] =
                        make_float2(acc[mt][nt][0], acc[mt][nt][1]);
                if (row + 8 < M)
                    *(float2*)&g_y1root[(size_t)(row + 8) * 64 + rc] =
                        make_float2(acc[mt][nt][2], acc[mt][nt][3]);
            }
        }
    }
}

// ---------------------------------------------------------------------------
// GEMM2 (tf32): [y2agg(fp16) | y2root(fp32)] = H @ [Wa; Wb]^T
// ---------------------------------------------------------------------------
__global__ __launch_bounds__(256) void gemm2(const float* __restrict__ Wa,
                                             const float* __restrict__ Wb,
                                             int M) {
    __shared__ unsigned As[128 * 36];
    __shared__ unsigned Bs[64 * 36];

    const int tid = threadIdx.x;
    const int lane = tid & 31;
    const int warp = tid >> 5;
    const int wm = (warp & 1) * 64;
    const int wn = (warp >> 1) * 16;
    const int m0 = blockIdx.x * 128;

    const int lr = tid >> 1;
    const int lcbase = (tid & 1) * 16;

    float acc[4][2][4];
#pragma unroll
    for (int a = 0; a < 4; a++)
#pragma unroll
        for (int b = 0; b < 2; b++)
#pragma unroll
            for (int f = 0; f < 4; f++) acc[a][b][f] = 0.f;

    for (int k0 = 0; k0 < 64; k0 += 32) {
        {
            int gm = m0 + lr;
#pragma unroll
            for (int i = 0; i < 4; i++) {
                int c = lcbase + i * 4;
                float4 v = make_float4(0.f, 0.f, 0.f, 0.f);
                if (gm < M) v = *(const float4*)&g_h[(size_t)gm * 64 + k0 + c];
                uint4 t = make_uint4(f2tf(v.x), f2tf(v.y), f2tf(v.z), f2tf(v.w));
                *(uint4*)&As[lr * 36 + c] = t;
            }
        }
        if (lr < 64) {
            const float* w = (lr < 32) ? (Wa + (size_t)lr * 64)
                                       : (Wb + (size_t)(lr - 32) * 64);
#pragma unroll
            for (int i = 0; i < 4; i++) {
                int c = lcbase + i * 4;
                float4 v = *(const float4*)&w[k0 + c];
                uint4 t = make_uint4(f2tf(v.x), f2tf(v.y), f2tf(v.z), f2tf(v.w));
                *(uint4*)&Bs[lr * 36 + c] = t;
            }
        }
        __syncthreads();

#pragma unroll
        for (int ks = 0; ks < 4; ks++) {
            const int kc = ks * 8;
            unsigned af[4][4], bf[2][2];
#pragma unroll
            for (int mt = 0; mt < 4; mt++) {
                int r = wm + mt * 16 + (lane >> 2);
                int c = kc + (lane & 3);
                af[mt][0] = As[r * 36 + c];
                af[mt][1] = As[(r + 8) * 36 + c];
                af[mt][2] = As[r * 36 + c + 4];
                af[mt][3] = As[(r + 8) * 36 + c + 4];
            }
#pragma unroll
            for (int nt = 0; nt < 2; nt++) {
                int n = wn + nt * 8 + (lane >> 2);
                bf[nt][0] = Bs[n * 36 + kc + (lane & 3)];
                bf[nt][1] = Bs[n * 36 + kc + 4 + (lane & 3)];
            }
#pragma unroll
            for (int mt = 0; mt < 4; mt++)
#pragma unroll
                for (int nt = 0; nt < 2; nt++)
                    mma_tf32(acc[mt][nt], af[mt], bf[nt]);
        }
        __syncthreads();
    }

#pragma unroll
    for (int mt = 0; mt < 4; mt++) {
#pragma unroll
        for (int nt = 0; nt < 2; nt++) {
            int row = m0 + wm + mt * 16 + (lane >> 2);
            int col = wn + nt * 8 + (lane & 3) * 2;
            if (col < 32) {
                __half2 h0 = __floats2half2_rn(acc[mt][nt][0], acc[mt][nt][1]);
                __half2 h1 = __floats2half2_rn(acc[mt][nt][2], acc[mt][nt][3]);
                if (row < M)
                    *(__half2*)&g_y2agg[(size_t)row * 32 + col] = h0;
                if (row + 8 < M)
                    *(__half2*)&g_y2agg[(size_t)(row + 8) * 32 + col] = h1;
            } else {
                int rc = col - 32;
                if (row < M)
                    *(float2*)&g_y2root[(size_t)row * 32 + rc] =
                        make_float2(acc[mt][nt][0], acc[mt][nt][1]);
                if (row + 8 < M)
                    *(float2*)&g_y2root[(size_t)(row + 8) * 32 + rc] =
                        make_float2(acc[mt][nt][2], acc[mt][nt][3]);
            }
        }
    }
}

// ---------------------------------------------------------------------------
// gather1: warp per dst. Row = 64 fp16 = 8 uint4. c8 x ns(0..3). fp32 acc.
// ---------------------------------------------------------------------------
__global__ __launch_bounds__(256) void gather1(const float4* __restrict__ b1,
                                               int M) {
    int w = (blockIdx.x * blockDim.x + threadIdx.x) >> 5;
    if (w >= M) return;
    int lane = threadIdx.x & 31;
    int c8 = lane & 7;
    int ns = lane >> 3;
    int beg = g_rowstart[w];
    int end = g_rowstart[w + 1];

    float a[8] = {0.f, 0.f, 0.f, 0.f, 0.f, 0.f, 0.f, 0.f};
    for (int j = beg + ns; j < end; j += 4) {
        int src = __ldg(&g_adj[j]);
        uint4 v = __ldg((const uint4*)g_y1agg + (size_t)src * 8 + c8);
        acc8(a, v);
    }
#pragma unroll
    for (int i = 0; i < 8; i++) {
        a[i] += __shfl_down_sync(0xffffffffu, a[i], 16);
        a[i] += __shfl_down_sync(0xffffffffu, a[i], 8);
    }

    if (ns == 0) {
        float inv = 1.0f / fmaxf((float)(end - beg), 1.0f);
        const float4* root = (const float4*)g_y1root + (size_t)w * 16 + c8 * 2;
        float4 r0 = __ldg(root);
        float4 r1 = __ldg(root + 1);
        float4 b0 = __ldg(&b1[c8 * 2]);
        float4 b1v = __ldg(&b1[c8 * 2 + 1]);
        float4 o0, o1;
        o0.x = fmaxf(fmaf(a[0], inv, b0.x + r0.x), 0.f);
        o0.y = fmaxf(fmaf(a[1], inv, b0.y + r0.y), 0.f);
        o0.z = fmaxf(fmaf(a[2], inv, b0.z + r0.z), 0.f);
        o0.w = fmaxf(fmaf(a[3], inv, b0.w + r0.w), 0.f);
        o1.x = fmaxf(fmaf(a[4], inv, b1v.x + r1.x), 0.f);
        o1.y = fmaxf(fmaf(a[5], inv, b1v.y + r1.y), 0.f);
        o1.z = fmaxf(fmaf(a[6], inv, b1v.z + r1.z), 0.f);
        o1.w = fmaxf(fmaf(a[7], inv, b1v.w + r1.w), 0.f);
        float4* hp = (float4*)g_h + (size_t)w * 16 + c8 * 2;
        hp[0] = o0;
        hp[1] = o1;
    }
}

// ---------------------------------------------------------------------------
// gather2: warp per dst. Row = 32 fp16 = 4 uint4. c4 x ns(0..7).
// ---------------------------------------------------------------------------
__global__ __launch_bounds__(256) void gather2(const float4* __restrict__ b2,
                                               float* __restrict__ out, int M) {
    int w = (blockIdx.x * blockDim.x + threadIdx.x) >> 5;
    if (w >= M) return;
    int lane = threadIdx.x & 31;
    int c4 = lane & 3;
    int ns = lane >> 2;
    int beg = g_rowstart[w];
    int end = g_rowstart[w + 1];

    float a[8] = {0.f, 0.f, 0.f, 0.f, 0.f, 0.f, 0.f, 0.f};
    for (int j = beg + ns; j < end; j += 8) {
        int src = __ldg(&g_adj[j]);
        uint4 v = __ldg((const uint4*)g_y2agg + (size_t)src * 4 + c4);
        acc8(a, v);
    }
#pragma unroll
    for (int i = 0; i < 8; i++) {
        a[i] += __shfl_down_sync(0xffffffffu, a[i], 16);
        a[i] += __shfl_down_sync(0xffffffffu, a[i], 8);
        a[i] += __shfl_down_sync(0xffffffffu, a[i], 4);
    }

    if (ns == 0) {
        float inv = 1.0f / fmaxf((float)(end - beg), 1.0f);
        const float4* root = (const float4*)g_y2root + (size_t)w * 8 + c4 * 2;
        float4 r0 = __ldg(root);
        float4 r1 = __ldg(root + 1);
        float4 b0 = __ldg(&b2[c4 * 2]);
        float4 b1v = __ldg(&b2[c4 * 2 + 1]);
        float4 o0, o1;
        o0.x = fmaf(a[0], inv, b0.x + r0.x);
        o0.y = fmaf(a[1], inv, b0.y + r0.y);
        o0.z = fmaf(a[2], inv, b0.z + r0.z);
        o0.w = fmaf(a[3], inv, b0.w + r0.w);
        o1.x = fmaf(a[4], inv, b1v.x + r1.x);
        o1.y = fmaf(a[5], inv, b1v.y + r1.y);
        o1.z = fmaf(a[6], inv, b1v.z + r1.z);
        o1.w = fmaf(a[7], inv, b1v.w + r1.w);
        float4* op = (float4*)out + (size_t)w * 8 + c4 * 2;
        op[0] = o0;
        op[1] = o1;
    }
}

// ---------------------------------------------------------------------------
static inline int cdiv(int a, int b) { return (a + b - 1) / b; }

extern "C" void kernel_launch(void* const* d_in, const int* in_sizes, int n_in,
                              void* d_out, int out_size) {
    const float* x    = (const float*)d_in[0];
    const void*  ei   = d_in[1];
    const float* W1l  = (const float*)d_in[2];
    const float* b1   = (const float*)d_in[3];
    const float* W1r  = (const float*)d_in[4];
    const float* W2l  = (const float*)d_in[5];
    const float* b2   = (const float*)d_in[6];
    const float* W2r  = (const float*)d_in[7];
    float* out = (float*)d_out;

    const int M  = in_sizes[0] / DIN;   // 100000
    const int nE = in_sizes[1] / 2;     // 1600000
    const int nB = cdiv(M, 256);

    static cudaStream_t s2 = nullptr;
    static cudaEvent_t evFork = nullptr, evJoin = nullptr;
    if (s2 == nullptr) {
        cudaStreamCreateWithFlags(&s2, cudaStreamNonBlocking);
        cudaEventCreateWithFlags(&evFork, cudaEventDisableTiming);
        cudaEventCreateWithFlags(&evJoin, cudaEventDisableTiming);
    }

    // Fork: CSR build on s2, gemm1 on default stream.
    cudaEventRecord(evFork, 0);
    cudaStreamWaitEvent(s2, evFork, 0);

    detect_kernel<<<1, 128, 0, s2>>>((const int*)ei, nE);
    zero_int<<<cdiv(M, 256), 256, 0, s2>>>(M);
    decode_kernel<<<cdiv(cdiv(nE, 4), 256), 256, 0, s2>>>(ei, nE);
    scanA<<<nB, 256, 0, s2>>>(M);
    scanB<<<1, 512, 0, s2>>>(nB);
    scanC<<<nB, 256, 0, s2>>>(M, nE);
    csr_fill<<<cdiv(cdiv(nE, 4), 256), 256, 0, s2>>>(ei, nE);

    gemm1<<<cdiv(M, 128), 256>>>(x, W1l, W1r, M);

    // Join: gather1 needs CSR (s2) and y1 (stream 0).
    cudaEventRecord(evJoin, s2);
    cudaStreamWaitEvent(0, evJoin, 0);

    gather1<<<cdiv(M * 32, 256), 256>>>((const float4*)b1, M);
    gemm2<<<cdiv(M, 128), 256>>>(W2l, W2r, M);
    gather2<<<cdiv(M * 32, 256), 256>>>((const float4*)b2, out, M);
}

// round 14
// speedup vs baseline: 1.8531x; 1.0367x over previous
#include <cuda_runtime.h>
#include <cuda_fp16.h>
#include <cstdint>

// GraphSAGE 2-layer, mean aggregation. Transform-then-aggregate + CSR-gather.
//   y1 = x @ [W1_l; W1_r]^T   (fp16 m16n8k16 mma, fp32 accumulate)
//   h  = relu(gather-mean(y1agg) + b1 + y1root)
//   y2 = h @ [W2_l; W2_r]^T
//   out= gather-mean(y2agg) + b2 + y2root
// fp16 inputs have the same eps (2^-11) as tf32 -> rel_err ~4e-4 (budget 1e-3)
// but HALF the MMA count and fragment-LDS per FLOP. CSR build overlaps gemm1.
// gemm1 submitted as the 6th launch so ncu (-s 5 -c 1) samples it.

#define MAXN 100000
#define MAXE 1600000
#define DIN 128
#define DH 64
#define DOUT 32

__device__ __align__(16) __half g_y1agg[MAXN * DH];      // [M][64] fp16
__device__ __align__(16) float  g_y1root[MAXN * DH];     // [M][64] fp32
__device__ __align__(16) float  g_h[MAXN * DH];          // [M][64]
__device__ __align__(16) __half g_y2agg[MAXN * DOUT];    // [M][32] fp16
__device__ __align__(16) float  g_y2root[MAXN * DOUT];   // [M][32] fp32
__device__ __align__(16) int    g_adj[MAXE];
__device__ __align__(16) int    g_rowstart[MAXN + 1];
__device__ __align__(16) int    g_degi[MAXN];
__device__ __align__(16) int    g_blocksums[512];
__device__ int g_is64;

// ---------------------------------------------------------------------------
__device__ __forceinline__ unsigned h2bits(float x, float y) {
    __half2 h = __floats2half2_rn(x, y);
    return *(unsigned*)&h;
}
__device__ __forceinline__ void mma_f16(float* c, const unsigned* a,
                                        const unsigned* b) {
    asm volatile(
        "mma.sync.aligned.m16n8k16.row.col.f32.f16.f16.f32 "
        "{%0,%1,%2,%3}, {%4,%5,%6,%7}, {%8,%9}, {%0,%1,%2,%3};"
        : "+f"(c[0]), "+f"(c[1]), "+f"(c[2]), "+f"(c[3])
        : "r"(a[0]), "r"(a[1]), "r"(a[2]), "r"(a[3]), "r"(b[0]), "r"(b[1]));
}
__device__ __forceinline__ void acc8(float* a, uint4 v) {
    float2 f0 = __half22float2(*(__half2*)&v.x);
    float2 f1 = __half22float2(*(__half2*)&v.y);
    float2 f2 = __half22float2(*(__half2*)&v.z);
    float2 f3 = __half22float2(*(__half2*)&v.w);
    a[0] += f0.x; a[1] += f0.y; a[2] += f1.x; a[3] += f1.y;
    a[4] += f2.x; a[5] += f2.y; a[6] += f3.x; a[7] += f3.y;
}

// ---------------------------------------------------------------------------
__global__ void detect_kernel(const int* __restrict__ ei32, int nE) {
    int n = nE < 128 ? nE : 128;
    int tid = threadIdx.x;
    int bad = (tid < n && ei32[2 * tid + 1] != 0) ? 1 : 0;
    unsigned m = __ballot_sync(0xffffffffu, bad);
    __shared__ unsigned s[4];
    if ((tid & 31) == 0) s[tid >> 5] = m;
    __syncthreads();
    if (tid == 0) g_is64 = ((s[0] | s[1] | s[2] | s[3]) == 0u) ? 1 : 0;
}

__global__ __launch_bounds__(256) void zero_int(int M) {
    int idx = blockIdx.x * blockDim.x + threadIdx.x;
    if (idx < M) g_degi[idx] = 0;
}

__global__ __launch_bounds__(256) void decode_kernel(const void* __restrict__ ei,
                                                     int nE) {
    int t = blockIdx.x * blockDim.x + threadIdx.x;
    int e0 = t * 4;
    if (e0 >= nE) return;
    if (g_is64) {
        const long long* p = (const long long*)ei + nE;
#pragma unroll
        for (int i = 0; i < 4; i++)
            if (e0 + i < nE) atomicAdd(&g_degi[(int)p[e0 + i]], 1);
    } else {
        const int* p = (const int*)ei + nE;
        if (e0 + 3 < nE) {
            int4 d = *(const int4*)&p[e0];
            atomicAdd(&g_degi[d.x], 1);
            atomicAdd(&g_degi[d.y], 1);
            atomicAdd(&g_degi[d.z], 1);
            atomicAdd(&g_degi[d.w], 1);
        } else {
            for (int i = 0; i < 4 && e0 + i < nE; i++)
                atomicAdd(&g_degi[p[e0 + i]], 1);
        }
    }
}

__global__ __launch_bounds__(256) void scanA(int M) {
    __shared__ int wsum[8];
    int tid = threadIdx.x;
    int lane = tid & 31;
    int warp = tid >> 5;
    int i = blockIdx.x * 256 + tid;
    int v = (i < M) ? g_degi[i] : 0;
    int x = v;
#pragma unroll
    for (int off = 1; off < 32; off <<= 1) {
        int t = __shfl_up_sync(0xffffffffu, x, off);
        if (lane >= off) x += t;
    }
    if (lane == 31) wsum[warp] = x;
    __syncthreads();
    if (warp == 0 && lane < 8) {
        int s = wsum[lane];
#pragma unroll
        for (int off = 1; off < 8; off <<= 1) {
            int t = __shfl_up_sync(0xffu, s, off, 8);
            if (lane >= off) s += t;
        }
        wsum[lane] = s;
    }
    __syncthreads();
    int base = (warp > 0) ? wsum[warp - 1] : 0;
    int incl = x + base;
    if (i < M) g_rowstart[i] = incl - v;
    if (tid == 255) g_blocksums[blockIdx.x] = incl;
}

__global__ void scanB(int nB) {
    __shared__ int wsum[16];
    int tid = threadIdx.x;
    int lane = tid & 31;
    int warp = tid >> 5;
    int v = (tid < nB) ? g_blocksums[tid] : 0;
    int x = v;
#pragma unroll
    for (int off = 1; off < 32; off <<= 1) {
        int t = __shfl_up_sync(0xffffffffu, x, off);
        if (lane >= off) x += t;
    }
    if (lane == 31) wsum[warp] = x;
    __syncthreads();
    if (warp == 0 && lane < 16) {
        int s = wsum[lane];
#pragma unroll
        for (int off = 1; off < 16; off <<= 1) {
            int t = __shfl_up_sync(0xffffu, s, off, 16);
            if (lane >= off) s += t;
        }
        wsum[lane] = s;
    }
    __syncthreads();
    int base = (warp > 0) ? wsum[warp - 1] : 0;
    if (tid < nB) g_blocksums[tid] = x + base - v;
}

__global__ __launch_bounds__(256) void scanC(int M, int nE) {
    int i = blockIdx.x * 256 + threadIdx.x;
    if (i < M) g_rowstart[i] += g_blocksums[blockIdx.x];
    if (i == 0) g_rowstart[M] = nE;
}

__global__ __launch_bounds__(256) void csr_fill(const void* __restrict__ ei,
                                                int nE) {
    int t = blockIdx.x * blockDim.x + threadIdx.x;
    int e0 = t * 4;
    if (e0 >= nE) return;
    int src[4], dst[4], n = 0;
    if (g_is64) {
        const long long* ps = (const long long*)ei;
        const long long* pd = ps + nE;
        for (int i = 0; i < 4 && e0 + i < nE; i++) {
            src[i] = (int)ps[e0 + i];
            dst[i] = (int)pd[e0 + i];
            n++;
        }
    } else {
        const int* ps = (const int*)ei;
        const int* pd = ps + nE;
        if (e0 + 3 < nE) {
            int4 s4 = *(const int4*)&ps[e0];
            int4 d4 = *(const int4*)&pd[e0];
            src[0] = s4.x; src[1] = s4.y; src[2] = s4.z; src[3] = s4.w;
            dst[0] = d4.x; dst[1] = d4.y; dst[2] = d4.z; dst[3] = d4.w;
            n = 4;
        } else {
            for (int i = 0; i < 4 && e0 + i < nE; i++) {
                src[i] = ps[e0 + i];
                dst[i] = pd[e0 + i];
                n++;
            }
        }
    }
#pragma unroll
    for (int i = 0; i < 4; i++) {
        if (i < n) {
            int pos = g_rowstart[dst[i]] + atomicSub(&g_degi[dst[i]], 1) - 1;
            g_adj[pos] = src[i];
        }
    }
}

// ---------------------------------------------------------------------------
// GEMM1 (fp16 m16n8k16): [y1agg(fp16) | y1root(fp32)] = X @ [Wa; Wb]^T
// BM=128, BN=128, BK=32 floats (=16 half2), 8 warps, warp tile 64x32.
// smem = half2 with row stride 20 (16 data + 4 pad; conflict-free frags).
// ---------------------------------------------------------------------------
__global__ __launch_bounds__(256) void gemm1(const float* __restrict__ X,
                                             const float* __restrict__ Wa,
                                             const float* __restrict__ Wb,
                                             int M) {
    __shared__ unsigned As[128 * 20];   // half2 bits
    __shared__ unsigned Bs[128 * 20];

    const int tid = threadIdx.x;
    const int lane = tid & 31;
    const int warp = tid >> 5;
    const int wm = (warp & 1) * 64;
    const int wn = (warp >> 1) * 32;
    const int m0 = blockIdx.x * 128;

    const int lr = tid >> 1;            // row 0..127
    const int lcbase = (tid & 1) * 16;  // float col base: 0 or 16

    float acc[4][4][4];
#pragma unroll
    for (int a = 0; a < 4; a++)
#pragma unroll
        for (int b = 0; b < 4; b++)
#pragma unroll
            for (int f = 0; f < 4; f++) acc[a][b][f] = 0.f;

    for (int k0 = 0; k0 < 128; k0 += 32) {
        {
            int gm = m0 + lr;
#pragma unroll
            for (int i = 0; i < 4; i++) {
                int c = lcbase + i * 4;             // float col
                float4 v = make_float4(0.f, 0.f, 0.f, 0.f);
                if (gm < M) v = *(const float4*)&X[(size_t)gm * 128 + k0 + c];
                uint2 t = make_uint2(h2bits(v.x, v.y), h2bits(v.z, v.w));
                *(uint2*)&As[lr * 20 + (c >> 1)] = t;
            }
        }
        {
            const float* w = (lr < 64) ? (Wa + (size_t)lr * 128)
                                       : (Wb + (size_t)(lr - 64) * 128);
#pragma unroll
            for (int i = 0; i < 4; i++) {
                int c = lcbase + i * 4;
                float4 v = *(const float4*)&w[k0 + c];
                uint2 t = make_uint2(h2bits(v.x, v.y), h2bits(v.z, v.w));
                *(uint2*)&Bs[lr * 20 + (c >> 1)] = t;
            }
        }
        __syncthreads();

#pragma unroll
        for (int ks = 0; ks < 2; ks++) {            // two k16 steps
            const int kc = ks * 8;                  // half2 offset
            unsigned af[4][4], bf[4][2];
#pragma unroll
            for (int mt = 0; mt < 4; mt++) {
                int r = wm + mt * 16 + (lane >> 2);
                int c = kc + (lane & 3);
                af[mt][0] = As[r * 20 + c];
                af[mt][1] = As[(r + 8) * 20 + c];
                af[mt][2] = As[r * 20 + c + 4];
                af[mt][3] = As[(r + 8) * 20 + c + 4];
            }
#pragma unroll
            for (int nt = 0; nt < 4; nt++) {
                int n = wn + nt * 8 + (lane >> 2);
                bf[nt][0] = Bs[n * 20 + kc + (lane & 3)];
                bf[nt][1] = Bs[n * 20 + kc + (lane & 3) + 4];
            }
#pragma unroll
            for (int mt = 0; mt < 4; mt++)
#pragma unroll
                for (int nt = 0; nt < 4; nt++)
                    mma_f16(acc[mt][nt], af[mt], bf[nt]);
        }
        __syncthreads();
    }

#pragma unroll
    for (int mt = 0; mt < 4; mt++) {
#pragma unroll
        for (int nt = 0; nt < 4; nt++) {
            int row = m0 + wm + mt * 16 + (lane >> 2);
            int col = wn + nt * 8 + (lane & 3) * 2;
            if (col < 64) {
                __half2 h0 = __floats2half2_rn(acc[mt][nt][0], acc[mt][nt][1]);
                __half2 h1 = __floats2half2_rn(acc[mt][nt][2], acc[mt][nt][3]);
                if (row < M)
                    *(__half2*)&g_y1agg[(size_t)row * 64 + col] = h0;
                if (row + 8 < M)
                    *(__half2*)&g_y1agg[(size_t)(row + 8) * 64 + col] = h1;
            } else {
                int rc = col - 64;
                if (row < M)
                    *(float2*)&g_y1root[(size_t)row * 64 + rc] =
                        make_float2(acc[mt][nt][0], acc[mt][nt][1]);
                if (row + 8 < M)
                    *(float2*)&g_y1root[(size_t)(row + 8) * 64 + rc] =
                        make_float2(acc[mt][nt][2], acc[mt][nt][3]);
            }
        }
    }
}

// ---------------------------------------------------------------------------
// GEMM2 (fp16): [y2agg(fp16) | y2root(fp32)] = H @ [Wa(32x64); Wb(32x64)]^T
// ---------------------------------------------------------------------------
__global__ __launch_bounds__(256) void gemm2(const float* __restrict__ Wa,
                                             const float* __restrict__ Wb,
                                             int M) {
    __shared__ unsigned As[128 * 20];
    __shared__ unsigned Bs[64 * 20];

    const int tid = threadIdx.x;
    const int lane = tid & 31;
    const int warp = tid >> 5;
    const int wm = (warp & 1) * 64;
    const int wn = (warp >> 1) * 16;
    const int m0 = blockIdx.x * 128;

    const int lr = tid >> 1;
    const int lcbase = (tid & 1) * 16;

    float acc[4][2][4];
#pragma unroll
    for (int a = 0; a < 4; a++)
#pragma unroll
        for (int b = 0; b < 2; b++)
#pragma unroll
            for (int f = 0; f < 4; f++) acc[a][b][f] = 0.f;

    for (int k0 = 0; k0 < 64; k0 += 32) {
        {
            int gm = m0 + lr;
#pragma unroll
            for (int i = 0; i < 4; i++) {
                int c = lcbase + i * 4;
                float4 v = make_float4(0.f, 0.f, 0.f, 0.f);
                if (gm < M) v = *(const float4*)&g_h[(size_t)gm * 64 + k0 + c];
                uint2 t = make_uint2(h2bits(v.x, v.y), h2bits(v.z, v.w));
                *(uint2*)&As[lr * 20 + (c >> 1)] = t;
            }
        }
        if (lr < 64) {
            const float* w = (lr < 32) ? (Wa + (size_t)lr * 64)
                                       : (Wb + (size_t)(lr - 32) * 64);
#pragma unroll
            for (int i = 0; i < 4; i++) {
                int c = lcbase + i * 4;
                float4 v = *(const float4*)&w[k0 + c];
                uint2 t = make_uint2(h2bits(v.x, v.y), h2bits(v.z, v.w));
                *(uint2*)&Bs[lr * 20 + (c >> 1)] = t;
            }
        }
        __syncthreads();

#pragma unroll
        for (int ks = 0; ks < 2; ks++) {
            const int kc = ks * 8;
            unsigned af[4][4], bf[2][2];
#pragma unroll
            for (int mt = 0; mt < 4; mt++) {
                int r = wm + mt * 16 + (lane >> 2);
                int c = kc + (lane & 3);
                af[mt][0] = As[r * 20 + c];
                af[mt][1] = As[(r + 8) * 20 + c];
                af[mt][2] = As[r * 20 + c + 4];
                af[mt][3] = As[(r + 8) * 20 + c + 4];
            }
#pragma unroll
            for (int nt = 0; nt < 2; nt++) {
                int n = wn + nt * 8 + (lane >> 2);
                bf[nt][0] = Bs[n * 20 + kc + (lane & 3)];
                bf[nt][1] = Bs[n * 20 + kc + (lane & 3) + 4];
            }
#pragma unroll
            for (int mt = 0; mt < 4; mt++)
#pragma unroll
                for (int nt = 0; nt < 2; nt++)
                    mma_f16(acc[mt][nt], af[mt], bf[nt]);
        }
        __syncthreads();
    }

#pragma unroll
    for (int mt = 0; mt < 4; mt++) {
#pragma unroll
        for (int nt = 0; nt < 2; nt++) {
            int row = m0 + wm + mt * 16 + (lane >> 2);
            int col = wn + nt * 8 + (lane & 3) * 2;
            if (col < 32) {
                __half2 h0 = __floats2half2_rn(acc[mt][nt][0], acc[mt][nt][1]);
                __half2 h1 = __floats2half2_rn(acc[mt][nt][2], acc[mt][nt][3]);
                if (row < M)
                    *(__half2*)&g_y2agg[(size_t)row * 32 + col] = h0;
                if (row + 8 < M)
                    *(__half2*)&g_y2agg[(size_t)(row + 8) * 32 + col] = h1;
            } else {
                int rc = col - 32;
                if (row < M)
                    *(float2*)&g_y2root[(size_t)row * 32 + rc] =
                        make_float2(acc[mt][nt][0], acc[mt][nt][1]);
                if (row + 8 < M)
                    *(float2*)&g_y2root[(size_t)(row + 8) * 32 + rc] =
                        make_float2(acc[mt][nt][2], acc[mt][nt][3]);
            }
        }
    }
}

// ---------------------------------------------------------------------------
// gather1: warp per dst. Row = 64 fp16 = 8 uint4. c8 x ns(0..3). fp32 acc.
// ---------------------------------------------------------------------------
__global__ __launch_bounds__(256) void gather1(const float4* __restrict__ b1,
                                               int M) {
    int w = (blockIdx.x * blockDim.x + threadIdx.x) >> 5;
    if (w >= M) return;
    int lane = threadIdx.x & 31;
    int c8 = lane & 7;
    int ns = lane >> 3;
    int beg = g_rowstart[w];
    int end = g_rowstart[w + 1];

    float a[8] = {0.f, 0.f, 0.f, 0.f, 0.f, 0.f, 0.f, 0.f};
    for (int j = beg + ns; j < end; j += 4) {
        int src = __ldg(&g_adj[j]);
        uint4 v = __ldg((const uint4*)g_y1agg + (size_t)src * 8 + c8);
        acc8(a, v);
    }
#pragma unroll
    for (int i = 0; i < 8; i++) {
        a[i] += __shfl_down_sync(0xffffffffu, a[i], 16);
        a[i] += __shfl_down_sync(0xffffffffu, a[i], 8);
    }

    if (ns == 0) {
        float inv = 1.0f / fmaxf((float)(end - beg), 1.0f);
        const float4* root = (const float4*)g_y1root + (size_t)w * 16 + c8 * 2;
        float4 r0 = __ldg(root);
        float4 r1 = __ldg(root + 1);
        float4 b0 = __ldg(&b1[c8 * 2]);
        float4 b1v = __ldg(&b1[c8 * 2 + 1]);
        float4 o0, o1;
        o0.x = fmaxf(fmaf(a[0], inv, b0.x + r0.x), 0.f);
        o0.y = fmaxf(fmaf(a[1], inv, b0.y + r0.y), 0.f);
        o0.z = fmaxf(fmaf(a[2], inv, b0.z + r0.z), 0.f);
        o0.w = fmaxf(fmaf(a[3], inv, b0.w + r0.w), 0.f);
        o1.x = fmaxf(fmaf(a[4], inv, b1v.x + r1.x), 0.f);
        o1.y = fmaxf(fmaf(a[5], inv, b1v.y + r1.y), 0.f);
        o1.z = fmaxf(fmaf(a[6], inv, b1v.z + r1.z), 0.f);
        o1.w = fmaxf(fmaf(a[7], inv, b1v.w + r1.w), 0.f);
        float4* hp = (float4*)g_h + (size_t)w * 16 + c8 * 2;
        hp[0] = o0;
        hp[1] = o1;
    }
}

// ---------------------------------------------------------------------------
// gather2: warp per dst. Row = 32 fp16 = 4 uint4. c4 x ns(0..7).
// ---------------------------------------------------------------------------
__global__ __launch_bounds__(256) void gather2(const float4* __restrict__ b2,
                                               float* __restrict__ out, int M) {
    int w = (blockIdx.x * blockDim.x + threadIdx.x) >> 5;
    if (w >= M) return;
    int lane = threadIdx.x & 31;
    int c4 = lane & 3;
    int ns = lane >> 2;
    int beg = g_rowstart[w];
    int end = g_rowstart[w + 1];

    float a[8] = {0.f, 0.f, 0.f, 0.f, 0.f, 0.f, 0.f, 0.f};
    for (int j = beg + ns; j < end; j += 8) {
        int src = __ldg(&g_adj[j]);
        uint4 v = __ldg((const uint4*)g_y2agg + (size_t)src * 4 + c4);
        acc8(a, v);
    }
#pragma unroll
    for (int i = 0; i < 8; i++) {
        a[i] += __shfl_down_sync(0xffffffffu, a[i], 16);
        a[i] += __shfl_down_sync(0xffffffffu, a[i], 8);
        a[i] += __shfl_down_sync(0xffffffffu, a[i], 4);
    }

    if (ns == 0) {
        float inv = 1.0f / fmaxf((float)(end - beg), 1.0f);
        const float4* root = (const float4*)g_y2root + (size_t)w * 8 + c4 * 2;
        float4 r0 = __ldg(root);
        float4 r1 = __ldg(root + 1);
        float4 b0 = __ldg(&b2[c4 * 2]);
        float4 b1v = __ldg(&b2[c4 * 2 + 1]);
        float4 o0, o1;
        o0.x = fmaf(a[0], inv, b0.x + r0.x);
        o0.y = fmaf(a[1], inv, b0.y + r0.y);
        o0.z = fmaf(a[2], inv, b0.z + r0.z);
        o0.w = fmaf(a[3], inv, b0.w + r0.w);
        o1.x = fmaf(a[4], inv, b1v.x + r1.x);
        o1.y = fmaf(a[5], inv, b1v.y + r1.y);
        o1.z = fmaf(a[6], inv, b1v.z + r1.z);
        o1.w = fmaf(a[7], inv, b1v.w + r1.w);
        float4* op = (float4*)out + (size_t)w * 8 + c4 * 2;
        op[0] = o0;
        op[1] = o1;
    }
}

// ---------------------------------------------------------------------------
static inline int cdiv(int a, int b) { return (a + b - 1) / b; }

extern "C" void kernel_launch(void* const* d_in, const int* in_sizes, int n_in,
                              void* d_out, int out_size) {
    const float* x    = (const float*)d_in[0];
    const void*  ei   = d_in[1];
    const float* W1l  = (const float*)d_in[2];
    const float* b1   = (const float*)d_in[3];
    const float* W1r  = (const float*)d_in[4];
    const float* W2l  = (const float*)d_in[5];
    const float* b2   = (const float*)d_in[6];
    const float* W2r  = (const float*)d_in[7];
    float* out = (float*)d_out;

    const int M  = in_sizes[0] / DIN;   // 100000
    const int nE = in_sizes[1] / 2;     // 1600000
    const int nB = cdiv(M, 256);

    static cudaStream_t s2 = nullptr;
    static cudaEvent_t evFork = nullptr, evJoin = nullptr;
    if (s2 == nullptr) {
        cudaStreamCreateWithFlags(&s2, cudaStreamNonBlocking);
        cudaEventCreateWithFlags(&evFork, cudaEventDisableTiming);
        cudaEventCreateWithFlags(&evJoin, cudaEventDisableTiming);
    }

    // Fork: CSR build on s2, gemm1 on default stream.
    cudaEventRecord(evFork, 0);
    cudaStreamWaitEvent(s2, evFork, 0);

    // Submission order puts gemm1 at launch #6 for ncu (-s 5 -c 1).
    detect_kernel<<<1, 128, 0, s2>>>((const int*)ei, nE);               // 1
    zero_int<<<cdiv(M, 256), 256, 0, s2>>>(M);                          // 2
    decode_kernel<<<cdiv(cdiv(nE, 4), 256), 256, 0, s2>>>(ei, nE);      // 3
    scanA<<<nB, 256, 0, s2>>>(M);                                       // 4
    scanB<<<1, 512, 0, s2>>>(nB);                                       // 5
    gemm1<<<cdiv(M, 128), 256>>>(x, W1l, W1r, M);                       // 6
    scanC<<<nB, 256, 0, s2>>>(M, nE);                                   // 7
    csr_fill<<<cdiv(cdiv(nE, 4), 256), 256, 0, s2>>>(ei, nE);           // 8

    // Join: gather1 needs CSR (s2) and y1 (stream 0).
    cudaEventRecord(evJoin, s2);
    cudaStreamWaitEvent(0, evJoin, 0);

    gather1<<<cdiv(M * 32, 256), 256>>>((const float4*)b1, M);
    gemm2<<<cdiv(M, 128), 256>>>(W2l, W2r, M);
    gather2<<<cdiv(M * 32, 256), 256>>>((const float4*)b2, out, M);
}